// round 11
// baseline (speedup 1.0000x reference)
#include <cuda_runtime.h>
#include <cuda_fp16.h>
#include <cstdint>
#include <math.h>

typedef unsigned int u32;

#define NN 32768
#define EE 262144
#define BB 8
#define HH 128
#define LL 6

// ---------------- scratch (device globals; no allocation) ----------------
__device__ __align__(16) float g_h[NN*HH];
__device__ __align__(16) float g_t1[NN*HH];
__device__ __align__(16) __half g_Ph[NN*HH];
__device__ __align__(16) __half g_Qh[NN*HH];
__device__ __align__(16) float g_R[NN*HH];
__device__ __align__(16) __half g_aggh[NN*HH];
__device__ __align__(16) __half g_Wm2h[LL*HH*HH];
__device__ float g_px[NN];
__device__ float g_pt[NN];
__device__ int   g_icnt[NN];
__device__ float g_inv[NN];
__device__ float g_meanb[BB*HH];
__device__ float g_sqb[BB*HH];
__device__ float g_gcnt[BB];

__device__ __forceinline__ float swishf(float x) {
    return x / (1.f + __expf(-x));
}

__device__ __forceinline__ u32 smem_u32(const void* p) {
    return (u32)__cvta_generic_to_shared(p);
}

__device__ __forceinline__ void ldsm4(u32& r0, u32& r1, u32& r2, u32& r3, u32 a) {
    asm volatile("ldmatrix.sync.aligned.m8n8.x4.shared.b16 {%0,%1,%2,%3}, [%4];"
                 : "=r"(r0), "=r"(r1), "=r"(r2), "=r"(r3) : "r"(a));
}

__device__ __forceinline__ void ldsm4t(u32& r0, u32& r1, u32& r2, u32& r3, u32 a) {
    asm volatile("ldmatrix.sync.aligned.m8n8.x4.trans.shared.b16 {%0,%1,%2,%3}, [%4];"
                 : "=r"(r0), "=r"(r1), "=r"(r2), "=r"(r3) : "r"(a));
}

__device__ __forceinline__ void mma16816(float* c, u32 a0, u32 a1, u32 a2, u32 a3,
                                         u32 b0, u32 b1) {
    asm volatile("mma.sync.aligned.m16n8k16.row.col.f32.f16.f16.f32 "
                 "{%0,%1,%2,%3}, {%4,%5,%6,%7}, {%8,%9}, {%0,%1,%2,%3};"
                 : "+f"(c[0]), "+f"(c[1]), "+f"(c[2]), "+f"(c[3])
                 : "r"(a0), "r"(a1), "r"(a2), "r"(a3), "r"(b0), "r"(b1));
}

// ---------------- zero / prep ----------------
__global__ void zero_prep() {
    int i = blockIdx.x * 256 + threadIdx.x;
    if (i < NN) g_icnt[i] = 0;
    if (i < BB) g_gcnt[i] = 0.f;
}

__global__ void zero_agg() {
    int i = blockIdx.x * 256 + threadIdx.x;   // over NN*HH/8 uint4s
    ((uint4*)g_aggh)[i] = make_uint4(0u, 0u, 0u, 0u);
}

__global__ void zero_stats() {
    int i = threadIdx.x + blockIdx.x * 256;
    if (i < BB*HH) { g_meanb[i] = 0.f; g_sqb[i] = 0.f; }
}

__global__ void prep_node(const float* __restrict__ pos, const int* __restrict__ batch) {
    int i = blockIdx.x * 256 + threadIdx.x;
    if (i < NN) {
        g_pt[i] = pos[2*i]   * 0.25f;
        g_px[i] = pos[2*i+1] * 0.0625f;
        atomicAdd(&g_gcnt[batch[i]], 1.f);
    }
}

__global__ void prep_edge(const int* __restrict__ eidx) {
    int e = blockIdx.x * 256 + threadIdx.x;
    if (e < EE) atomicAdd(&g_icnt[eidx[EE + e]], 1);
}

__global__ void fin_cnt() {
    int i = blockIdx.x * 256 + threadIdx.x;
    if (i < NN) g_inv[i] = 1.f / (float)max(g_icnt[i], 1);
}

// convert all 6 layers of Wm2 to fp16 (49152 half2)
__global__ void convert_wm2(const float* __restrict__ Wm2) {
    int i = blockIdx.x * 256 + threadIdx.x;   // over LL*HH*HH/2
    float2 v = ((const float2*)Wm2)[i];
    ((__half2*)g_Wm2h)[i] = __floats2half2_rn(v.x, v.y);
}

// ---------------- small per-node kernels ----------------
__global__ void encoder1(const float* __restrict__ u, const float* __restrict__ We1,
                         const float* __restrict__ be1) {
    __shared__ float s[27];
    int n = blockIdx.x;
    int t = threadIdx.x;
    if (t < 25)       s[t]  = u[n*25 + t];
    else if (t == 25) s[25] = g_px[n];
    else if (t == 26) s[26] = g_pt[n];
    __syncthreads();
    float a = __ldg(&be1[t]);
    #pragma unroll
    for (int k = 0; k < 27; k++) a += s[k] * __ldg(&We1[k*128 + t]);
    g_t1[n*128 + t] = swishf(a);
}

__global__ void rkern(const float* __restrict__ u, const float* __restrict__ Wm1l) {
    __shared__ float s[26];
    int n = blockIdx.x;
    int t = threadIdx.x;
    if (t < 25)       s[t]  = u[n*25 + t];
    else if (t == 25) s[25] = g_px[n];
    __syncthreads();
    float a = 0.f;
    #pragma unroll
    for (int k = 0; k < 25; k++) a += s[k] * __ldg(&Wm1l[(256+k)*128 + t]);
    a += s[25] * __ldg(&Wm1l[281*128 + t]);
    g_R[n*128 + t] = a;
}

// ---------------- tensor-core node GEMM: 64 rows x 128 cols ----------------
// modes: 0: swish(acc+b) ->out    1: acc+R+pt*wx+b ->outh(fp16)   2: acc-R ->outh(fp16)
//        3: swish(acc+pt*wx+b) ->out [K=256, A2h (fp16 agg) scaled by inv]
//        4: out += swish(acc+b)
__global__ void mlp16(const float* __restrict__ A, const __half* __restrict__ A2h,
                      const float* __restrict__ W, const float* __restrict__ bias,
                      const float* __restrict__ Rm, const float* __restrict__ wx,
                      float* __restrict__ out, __half* __restrict__ outh,
                      int K, int mode) {
    extern __shared__ __align__(16) char smbuf[];
    __half* Wh = (__half*)smbuf;            // K x 136
    __half* Ah = Wh + K*136;                // 64 x (K+8)
    const int PA = K + 8;

    int tid = threadIdx.x;
    int r0g = blockIdx.x * 64;

    for (int i = tid; i < K*32; i += 256) {
        int k = i >> 5;
        int c4 = (i & 31) << 2;
        float4 v = *(const float4*)&W[k*128 + c4];
        __half2* dst = (__half2*)&Wh[k*136 + c4];
        dst[0] = __floats2half2_rn(v.x, v.y);
        dst[1] = __floats2half2_rn(v.z, v.w);
    }
    int kq = K >> 2;
    int sh = (K == 256) ? 6 : 5;
    for (int i = tid; i < (64 << sh); i += 256) {
        int r  = i >> sh;
        int k4 = (i & (kq - 1)) << 2;
        int row = r0g + r;
        float4 v;
        if (k4 < 128) {
            v = *(const float4*)&A[row*128 + k4];
        } else {
            uint2 hv = *(const uint2*)&A2h[row*128 + (k4 - 128)];
            __half2* hp = (__half2*)&hv;
            float2 f0 = __half22float2(hp[0]);
            float2 f1 = __half22float2(hp[1]);
            float s = g_inv[row];
            v = make_float4(f0.x*s, f0.y*s, f1.x*s, f1.y*s);
        }
        __half2* dst = (__half2*)&Ah[r*PA + k4];
        dst[0] = __floats2half2_rn(v.x, v.y);
        dst[1] = __floats2half2_rn(v.z, v.w);
    }
    __syncthreads();

    int w = tid >> 5;
    int lane = tid & 31;
    int wm = (w & 3) * 16;
    int wn = (w >> 2) * 64;
    int grp = lane >> 2;
    int qt  = lane & 3;
    int lr = lane & 7;
    int lm = lane >> 3;

    float acc[8][4];
    #pragma unroll
    for (int j = 0; j < 8; j++) {
        #pragma unroll
        for (int i = 0; i < 4; i++) acc[j][i] = 0.f;
    }

    u32 a_base = smem_u32(Ah) + (u32)(((wm + (lm & 1)*8 + lr)*PA + (lm >> 1)*8) * 2);
    u32 b_base = smem_u32(Wh) + (u32)((((lm & 1)*8 + lr)*136 + wn + (lm >> 1)*8) * 2);

    int kit = K >> 4;
    for (int kk = 0; kk < kit; kk++) {
        u32 a0, a1, a2, a3;
        ldsm4(a0, a1, a2, a3, a_base + (u32)(kk*32));
        #pragma unroll
        for (int j = 0; j < 4; j++) {
            u32 b0, b1, b2, b3;
            ldsm4t(b0, b1, b2, b3, b_base + (u32)(kk*4352 + j*32));
            mma16816(acc[2*j],     a0, a1, a2, a3, b0, b1);
            mma16816(acc[2*j + 1], a0, a1, a2, a3, b2, b3);
        }
    }

    #pragma unroll
    for (int j = 0; j < 8; j++) {
        int col = wn + j*8 + 2*qt;
        int r0 = r0g + wm + grp;
        int r1 = r0 + 8;
        float a0 = acc[j][0], a1 = acc[j][1], a2 = acc[j][2], a3 = acc[j][3];
        if (mode == 0) {
            float o0 = swishf(a0 + __ldg(&bias[col]));
            float o1 = swishf(a1 + __ldg(&bias[col+1]));
            float o2 = swishf(a2 + __ldg(&bias[col]));
            float o3 = swishf(a3 + __ldg(&bias[col+1]));
            *(float2*)&out[r0*128 + col] = make_float2(o0, o1);
            *(float2*)&out[r1*128 + col] = make_float2(o2, o3);
        } else if (mode == 1) {
            float pt0 = g_pt[r0], pt1 = g_pt[r1];
            float o0 = a0 + Rm[r0*128 + col]   + pt0*__ldg(&wx[col])   + __ldg(&bias[col]);
            float o1 = a1 + Rm[r0*128 + col+1] + pt0*__ldg(&wx[col+1]) + __ldg(&bias[col+1]);
            float o2 = a2 + Rm[r1*128 + col]   + pt1*__ldg(&wx[col])   + __ldg(&bias[col]);
            float o3 = a3 + Rm[r1*128 + col+1] + pt1*__ldg(&wx[col+1]) + __ldg(&bias[col+1]);
            *(__half2*)&outh[r0*128 + col] = __floats2half2_rn(o0, o1);
            *(__half2*)&outh[r1*128 + col] = __floats2half2_rn(o2, o3);
        } else if (mode == 2) {
            float o0 = a0 - Rm[r0*128 + col];
            float o1 = a1 - Rm[r0*128 + col+1];
            float o2 = a2 - Rm[r1*128 + col];
            float o3 = a3 - Rm[r1*128 + col+1];
            *(__half2*)&outh[r0*128 + col] = __floats2half2_rn(o0, o1);
            *(__half2*)&outh[r1*128 + col] = __floats2half2_rn(o2, o3);
        } else if (mode == 3) {
            float pt0 = g_pt[r0], pt1 = g_pt[r1];
            float o0 = swishf(a0 + pt0*__ldg(&wx[col])   + __ldg(&bias[col]));
            float o1 = swishf(a1 + pt0*__ldg(&wx[col+1]) + __ldg(&bias[col+1]));
            float o2 = swishf(a2 + pt1*__ldg(&wx[col])   + __ldg(&bias[col]));
            float o3 = swishf(a3 + pt1*__ldg(&wx[col+1]) + __ldg(&bias[col+1]));
            *(float2*)&out[r0*128 + col] = make_float2(o0, o1);
            *(float2*)&out[r1*128 + col] = make_float2(o2, o3);
        } else {
            float o0 = out[r0*128 + col]   + swishf(a0 + __ldg(&bias[col]));
            float o1 = out[r0*128 + col+1] + swishf(a1 + __ldg(&bias[col+1]));
            float o2 = out[r1*128 + col]   + swishf(a2 + __ldg(&bias[col]));
            float o3 = out[r1*128 + col+1] + swishf(a3 + __ldg(&bias[col+1]));
            *(float2*)&out[r0*128 + col] = make_float2(o0, o1);
            *(float2*)&out[r1*128 + col] = make_float2(o2, o3);
        }
    }
}

// ---------------- fused edge kernel: persistent W, fp16 gathers, f16x2 packed reductions ----------------
// smem: Wh 128x136 half (34816B) | Mh 64x136 half (17408B) | st,ss 64+64 int (512B)  => ~52.7KB -> 4 blocks/SM
#define EDGE_SMEM (34816 + 17408 + 512)
#define EDGE_GRID 512
__global__ void edge_kernel(const int* __restrict__ eidx,
                            const __half* __restrict__ Whg,
                            const float* __restrict__ bm2l) {
    extern __shared__ __align__(16) char smbuf[];
    __half* Wh = (__half*)smbuf;                       // 128 x 136
    __half* Mh = (__half*)(smbuf + 34816);             // 64 x 136
    int*    st = (int*)(smbuf + 34816 + 17408);
    int*    se = st + 64;

    int tid = threadIdx.x;

    // stage W once per block (fp16 global -> smem pitch 136)
    for (int i = tid; i < 128*16; i += 256) {
        int r = i >> 4;
        int c8 = (i & 15) << 3;
        uint4 v = *(const uint4*)&Whg[r*128 + c8];
        *(uint4*)&Wh[r*136 + c8] = v;
    }

    int w = tid >> 5;
    int lane = tid & 31;
    int wm = (w & 3) * 16;
    int wn = (w >> 2) * 64;
    int grp = lane >> 2;
    int qt  = lane & 3;
    int lr = lane & 7;
    int lm = lane >> 3;

    u32 a_base = smem_u32(Mh) + (u32)(((wm + (lm & 1)*8 + lr)*136 + (lm >> 1)*8) * 2);
    u32 b_base = smem_u32(Wh) + (u32)((((lm & 1)*8 + lr)*136 + wn + (lm >> 1)*8) * 2);

    for (int tile = blockIdx.x; tile < EE/64; tile += EDGE_GRID) {
        int e0 = tile * 64;
        __syncthreads();   // protect st/se and Mh from previous iteration readers
        if (tid < 64) {
            se[tid] = eidx[e0 + tid];
            st[tid] = eidx[EE + e0 + tid];
        }
        __syncthreads();

        // gather + first swish -> fp16 messages
        for (int i = tid; i < 64*16; i += 256) {
            int e = i >> 4;
            int c8 = (i & 15) << 3;
            uint4 pv = *(const uint4*)&g_Ph[st[e]*128 + c8];
            uint4 qv = *(const uint4*)&g_Qh[se[e]*128 + c8];
            __half2* ph = (__half2*)&pv;
            __half2* qh = (__half2*)&qv;
            uint4 ov;
            __half2* oh = (__half2*)&ov;
            #pragma unroll
            for (int k2 = 0; k2 < 4; k2++) {
                float2 p2 = __half22float2(ph[k2]);
                float2 q2 = __half22float2(qh[k2]);
                oh[k2] = __floats2half2_rn(swishf(p2.x + q2.x), swishf(p2.y + q2.y));
            }
            *(uint4*)&Mh[e*136 + c8] = ov;
        }
        __syncthreads();

        float acc[8][4];
        #pragma unroll
        for (int j = 0; j < 8; j++) {
            #pragma unroll
            for (int i = 0; i < 4; i++) acc[j][i] = 0.f;
        }

        #pragma unroll
        for (int kk = 0; kk < 8; kk++) {
            u32 a0, a1, a2, a3;
            ldsm4(a0, a1, a2, a3, a_base + (u32)(kk*32));
            #pragma unroll
            for (int j = 0; j < 4; j++) {
                u32 b0, b1, b2, b3;
                ldsm4t(b0, b1, b2, b3, b_base + (u32)(kk*4352 + j*32));
                mma16816(acc[2*j],     a0, a1, a2, a3, b0, b1);
                mma16816(acc[2*j + 1], a0, a1, a2, a3, b2, b3);
            }
        }

        // second swish + packed f16x2 scatter-add (one RED lane per col pair)
        int er0 = wm + grp;
        int er1 = er0 + 8;
        int t0 = st[er0];
        int t1 = st[er1];
        #pragma unroll
        for (int j = 0; j < 8; j++) {
            int col = wn + j*8 + 2*qt;
            float b0v = __ldg(&bm2l[col]);
            float b1v = __ldg(&bm2l[col + 1]);
            __half2 v0 = __floats2half2_rn(swishf(acc[j][0] + b0v), swishf(acc[j][1] + b1v));
            __half2 v1 = __floats2half2_rn(swishf(acc[j][2] + b0v), swishf(acc[j][3] + b1v));
            atomicAdd((__half2*)&g_aggh[t0*128 + col], v0);
            atomicAdd((__half2*)&g_aggh[t1*128 + col], v1);
        }
    }
}

// ---------------- per-batch norm ----------------
__global__ void norm_reduce(const int* __restrict__ batch) {
    int c = threadIdx.x;
    int base = blockIdx.x * 128;
    float s = 0.f, q = 0.f;
    for (int r = 0; r < 128; r++) {
        float v = g_h[(base + r)*128 + c];
        s += v;
        q += v*v;
    }
    int b = batch[base];
    atomicAdd(&g_meanb[b*128 + c], s);
    atomicAdd(&g_sqb[b*128 + c], q);
}

__global__ void norm_apply(const int* __restrict__ batch) {
    int i = blockIdx.x * 256 + threadIdx.x;
    int node = i >> 7;
    int c = i & 127;
    int b = batch[node];
    float gi = 1.f / g_gcnt[b];
    float m = g_meanb[b*128 + c] * gi;
    float var = g_sqb[b*128 + c] * gi - m*m;
    g_h[i] = (g_h[i] - m) * rsqrtf(var + 1e-5f);
}

// ---------------- conv decoder ----------------
__global__ void decoder(const float* __restrict__ u,
                        const float* __restrict__ Wc1, const float* __restrict__ bc1,
                        const float* __restrict__ Wc2, const float* __restrict__ bc2,
                        float* __restrict__ out) {
    __shared__ float hr[128];
    __shared__ float c1[8*38];
    int n = blockIdx.x;
    int tid = threadIdx.x;
    for (int i = tid; i < 128; i += 64) hr[i] = g_h[n*128 + i];
    __syncthreads();
    for (int i = tid; i < 8*38; i += 64) {
        int ch = i / 38;
        int p = i % 38;
        float a = __ldg(&bc1[ch]);
        #pragma unroll
        for (int k = 0; k < 16; k++) a += hr[3*p + k] * __ldg(&Wc1[ch*16 + k]);
        c1[i] = swishf(a);
    }
    __syncthreads();
    if (tid < 25) {
        float a = __ldg(&bc2[0]);
        #pragma unroll
        for (int c = 0; c < 8; c++) {
            #pragma unroll
            for (int k = 0; k < 14; k++)
                a += c1[c*38 + tid + k] * __ldg(&Wc2[c*14 + k]);
        }
        float dt = 4.0f / 250.0f;
        out[n*25 + tid] = u[n*25 + 24] + (float)(tid + 1) * dt * a;
    }
}

// ---------------- host ----------------
extern "C" void kernel_launch(void* const* d_in, const int* in_sizes, int n_in,
                              void* d_out, int out_size) {
    const float* u     = (const float*)d_in[0];
    const float* pos   = (const float*)d_in[1];
    const int*   eidx  = (const int*)d_in[2];
    const int*   batch = (const int*)d_in[3];
    const float* We1 = (const float*)d_in[4];
    const float* be1 = (const float*)d_in[5];
    const float* We2 = (const float*)d_in[6];
    const float* be2 = (const float*)d_in[7];
    const float* Wm1 = (const float*)d_in[8];
    const float* bm1 = (const float*)d_in[9];
    const float* Wm2 = (const float*)d_in[10];
    const float* bm2 = (const float*)d_in[11];
    const float* Wu1 = (const float*)d_in[12];
    const float* bu1 = (const float*)d_in[13];
    const float* Wu2 = (const float*)d_in[14];
    const float* bu2 = (const float*)d_in[15];
    const float* Wc1 = (const float*)d_in[16];
    const float* bc1 = (const float*)d_in[17];
    const float* Wc2 = (const float*)d_in[18];
    const float* bc2 = (const float*)d_in[19];
    float* out = (float*)d_out;

    void *a_h = 0, *a_t1 = 0, *a_Ph = 0, *a_Qh = 0, *a_R = 0, *a_aggh = 0, *a_wm2h = 0;
    cudaGetSymbolAddress(&a_h,    g_h);
    cudaGetSymbolAddress(&a_t1,   g_t1);
    cudaGetSymbolAddress(&a_Ph,   g_Ph);
    cudaGetSymbolAddress(&a_Qh,   g_Qh);
    cudaGetSymbolAddress(&a_R,    g_R);
    cudaGetSymbolAddress(&a_aggh, g_aggh);
    cudaGetSymbolAddress(&a_wm2h, g_Wm2h);
    float*  h    = (float*)a_h;
    float*  t1   = (float*)a_t1;
    __half* Ph   = (__half*)a_Ph;
    __half* Qh   = (__half*)a_Qh;
    float*  R    = (float*)a_R;
    __half* aggh = (__half*)a_aggh;
    __half* Wm2h = (__half*)a_wm2h;

    int MLP_SMEM_MAX = (256*136 + 64*264) * 2;   // K=256 case
    int MLP_SMEM_128 = (128*136 + 64*136) * 2;
    cudaFuncSetAttribute(mlp16, cudaFuncAttributeMaxDynamicSharedMemorySize, MLP_SMEM_MAX);
    cudaFuncSetAttribute(edge_kernel, cudaFuncAttributeMaxDynamicSharedMemorySize, EDGE_SMEM);

    convert_wm2<<<(LL*HH*HH/2)/256, 256>>>(Wm2);
    zero_prep<<<NN/256, 256>>>();
    prep_node<<<NN/256, 256>>>(pos, batch);
    prep_edge<<<EE/256, 256>>>(eidx);
    fin_cnt<<<NN/256, 256>>>();

    encoder1<<<NN, 128>>>(u, We1, be1);
    mlp16<<<NN/64, 256, MLP_SMEM_128>>>(t1, (const __half*)0, We2, be2, (const float*)0, (const float*)0, h, (__half*)0, 128, 0);

    for (int l = 0; l < LL; l++) {
        const float* Wm1l = Wm1 + (size_t)l * 283 * 128;
        const float* Wu1l = Wu1 + (size_t)l * 257 * 128;
        const float* Wu2l = Wu2 + (size_t)l * 128 * 128;

        rkern<<<NN, 128>>>(u, Wm1l);
        mlp16<<<NN/64, 256, MLP_SMEM_128>>>(h, (const __half*)0, Wm1l, bm1 + l*128, R, Wm1l + 282*128, (float*)0, Ph, 128, 1);
        mlp16<<<NN/64, 256, MLP_SMEM_128>>>(h, (const __half*)0, Wm1l + 128*128, (const float*)0, R, (const float*)0, (float*)0, Qh, 128, 2);

        zero_agg<<<(NN*HH/8)/256, 256>>>();
        edge_kernel<<<EDGE_GRID, 256, EDGE_SMEM>>>(eidx, Wm2h + (size_t)l*HH*HH, bm2 + l*128);

        mlp16<<<NN/64, 256, MLP_SMEM_MAX>>>(h, aggh, Wu1l, bu1 + l*128, (const float*)0, Wu1l + 256*128, t1, (__half*)0, 256, 3);
        mlp16<<<NN/64, 256, MLP_SMEM_128>>>(t1, (const __half*)0, Wu2l, bu2 + l*128, (const float*)0, (const float*)0, h, (__half*)0, 128, 4);

        zero_stats<<<(BB*HH + 255)/256, 256>>>();
        norm_reduce<<<NN/128, 128>>>(batch);
        norm_apply<<<(NN*HH)/256, 256>>>(batch);
    }

    decoder<<<NN, 64>>>(u, Wc1, bc1, Wc2, bc2, out);
}

// round 13
// speedup vs baseline: 1.2436x; 1.2436x over previous
#include <cuda_runtime.h>
#include <cuda_fp16.h>
#include <cstdint>
#include <math.h>

typedef unsigned int u32;

#define NN 32768
#define EE 262144
#define BB 8
#define HH 128
#define LL 6

// ---------------- scratch (device globals; no allocation) ----------------
__device__ __align__(16) float g_h[NN*HH];
__device__ __align__(16) float g_t1[NN*HH];
__device__ __align__(16) __half g_Ph[NN*HH];
__device__ __align__(16) __half g_Qh[NN*HH];
__device__ __align__(16) float g_agg[NN*HH];
__device__ __align__(16) __half g_Wm2h[LL*HH*HH];
__device__ __align__(16) __half g_WPh[LL*160*128];
__device__ __align__(16) __half g_WQh[LL*160*128];
__device__ __align__(16) __half g_Wu1h[LL*256*128];
__device__ __align__(16) __half g_Wu2h[LL*128*128];
__device__ float g_px[NN];
__device__ float g_pt[NN];
__device__ int   g_icnt[NN];
__device__ float g_inv[NN];
__device__ float g_meanb[BB*HH];
__device__ float g_sqb[BB*HH];
__device__ float g_gcnt[BB];

__device__ __forceinline__ float swishf(float x) {
    return x / (1.f + __expf(-x));
}

__device__ __forceinline__ u32 smem_u32(const void* p) {
    return (u32)__cvta_generic_to_shared(p);
}

__device__ __forceinline__ void ldsm4(u32& r0, u32& r1, u32& r2, u32& r3, u32 a) {
    asm volatile("ldmatrix.sync.aligned.m8n8.x4.shared.b16 {%0,%1,%2,%3}, [%4];"
                 : "=r"(r0), "=r"(r1), "=r"(r2), "=r"(r3) : "r"(a));
}

__device__ __forceinline__ void ldsm4t(u32& r0, u32& r1, u32& r2, u32& r3, u32 a) {
    asm volatile("ldmatrix.sync.aligned.m8n8.x4.trans.shared.b16 {%0,%1,%2,%3}, [%4];"
                 : "=r"(r0), "=r"(r1), "=r"(r2), "=r"(r3) : "r"(a));
}

__device__ __forceinline__ void mma16816(float* c, u32 a0, u32 a1, u32 a2, u32 a3,
                                         u32 b0, u32 b1) {
    asm volatile("mma.sync.aligned.m16n8k16.row.col.f32.f16.f16.f32 "
                 "{%0,%1,%2,%3}, {%4,%5,%6,%7}, {%8,%9}, {%0,%1,%2,%3};"
                 : "+f"(c[0]), "+f"(c[1]), "+f"(c[2]), "+f"(c[3])
                 : "r"(a0), "r"(a1), "r"(a2), "r"(a3), "r"(b0), "r"(b1));
}

// ---------------- zero / prep ----------------
__global__ void zero_prep() {
    int i = blockIdx.x * 256 + threadIdx.x;
    if (i < NN) g_icnt[i] = 0;
    if (i < BB) g_gcnt[i] = 0.f;
}

__global__ void zero_agg() {
    int i = blockIdx.x * 256 + threadIdx.x;   // over NN*HH/4
    ((float4*)g_agg)[i] = make_float4(0.f, 0.f, 0.f, 0.f);
}

__global__ void zero_stats() {
    int i = threadIdx.x + blockIdx.x * 256;
    if (i < BB*HH) { g_meanb[i] = 0.f; g_sqb[i] = 0.f; }
}

__global__ void prep_node(const float* __restrict__ pos, const int* __restrict__ batch) {
    int i = blockIdx.x * 256 + threadIdx.x;
    if (i < NN) {
        g_pt[i] = pos[2*i]   * 0.25f;
        g_px[i] = pos[2*i+1] * 0.0625f;
        atomicAdd(&g_gcnt[batch[i]], 1.f);
    }
}

__global__ void prep_edge(const int* __restrict__ eidx) {
    int e = blockIdx.x * 256 + threadIdx.x;
    if (e < EE) atomicAdd(&g_icnt[eidx[EE + e]], 1);
}

__global__ void fin_cnt() {
    int i = blockIdx.x * 256 + threadIdx.x;
    if (i < NN) g_inv[i] = 1.f / (float)max(g_icnt[i], 1);
}

__global__ void convert_wm2(const float* __restrict__ Wm2) {
    int i = blockIdx.x * 256 + threadIdx.x;   // over LL*HH*HH/2
    float2 v = ((const float2*)Wm2)[i];
    ((__half2*)g_Wm2h)[i] = __floats2half2_rn(v.x, v.y);
}

// build folded P/Q weights
__global__ void build_pq_w(const float* __restrict__ Wm1, const float* __restrict__ bm1) {
    int i = blockIdx.x * 256 + threadIdx.x;   // over LL*160*128
    if (i >= LL*160*128) return;
    int l = i / (160*128);
    int r = (i / 128) % 160;
    int c = i & 127;
    const float* W = Wm1 + (size_t)l * 283 * 128;
    float p, q;
    if (r < 128)       { p = W[r*128 + c];              q = W[(128 + r)*128 + c]; }
    else if (r < 153)  { float v = W[(256 + r - 128)*128 + c]; p = v; q = -v; }
    else if (r == 153) { float v = W[281*128 + c];      p = v; q = -v; }
    else if (r == 154) { p = W[282*128 + c];            q = 0.f; }
    else if (r == 155) { p = bm1[l*128 + c];            q = 0.f; }
    else               { p = 0.f;                        q = 0.f; }
    g_WPh[i] = __float2half(p);
    g_WQh[i] = __float2half(q);
}

__global__ void build_u_w(const float* __restrict__ Wu1, const float* __restrict__ Wu2) {
    int i = blockIdx.x * 256 + threadIdx.x;   // over LL*256*128
    if (i >= LL*256*128) return;
    int l = i / (256*128);
    int rc = i % (256*128);
    g_Wu1h[i] = __float2half(Wu1[(size_t)l*257*128 + rc]);
    if (rc < 128*128) g_Wu2h[(size_t)l*128*128 + rc] = __float2half(Wu2[(size_t)l*128*128 + rc]);
}

// ---------------- encoder ----------------
__global__ void encoder1(const float* __restrict__ u, const float* __restrict__ We1,
                         const float* __restrict__ be1) {
    __shared__ float s[27];
    int n = blockIdx.x;
    int t = threadIdx.x;
    if (t < 25)       s[t]  = u[n*25 + t];
    else if (t == 25) s[25] = g_px[n];
    else if (t == 26) s[26] = g_pt[n];
    __syncthreads();
    float a = __ldg(&be1[t]);
    #pragma unroll
    for (int k = 0; k < 27; k++) a += s[k] * __ldg(&We1[k*128 + t]);
    g_t1[n*128 + t] = swishf(a);
}

// generic fp16 GEMM (encoder second layer): out = swish(A@W + b)
__global__ void mlp16(const float* __restrict__ A,
                      const float* __restrict__ W, const float* __restrict__ bias,
                      float* __restrict__ out) {
    extern __shared__ __align__(16) char smbuf[];
    __half* Wh = (__half*)smbuf;            // 128 x 136
    __half* Ah = Wh + 128*136;              // 64 x 136
    const int PA = 136;

    int tid = threadIdx.x;
    int r0g = blockIdx.x * 64;

    for (int i = tid; i < 128*32; i += 256) {
        int k = i >> 5;
        int c4 = (i & 31) << 2;
        float4 v = *(const float4*)&W[k*128 + c4];
        __half2* dst = (__half2*)&Wh[k*136 + c4];
        dst[0] = __floats2half2_rn(v.x, v.y);
        dst[1] = __floats2half2_rn(v.z, v.w);
    }
    for (int i = tid; i < 64*32; i += 256) {
        int r  = i >> 5;
        int k4 = (i & 31) << 2;
        float4 v = *(const float4*)&A[(r0g + r)*128 + k4];
        __half2* dst = (__half2*)&Ah[r*PA + k4];
        dst[0] = __floats2half2_rn(v.x, v.y);
        dst[1] = __floats2half2_rn(v.z, v.w);
    }
    __syncthreads();

    int w = tid >> 5;
    int lane = tid & 31;
    int wm = (w & 3) * 16;
    int wn = (w >> 2) * 64;
    int grp = lane >> 2;
    int qt  = lane & 3;
    int lr = lane & 7;
    int lm = lane >> 3;

    float acc[8][4];
    #pragma unroll
    for (int j = 0; j < 8; j++) {
        #pragma unroll
        for (int i = 0; i < 4; i++) acc[j][i] = 0.f;
    }

    u32 a_base = smem_u32(Ah) + (u32)(((wm + (lm & 1)*8 + lr)*PA + (lm >> 1)*8) * 2);
    u32 b_base = smem_u32(Wh) + (u32)((((lm & 1)*8 + lr)*136 + wn + (lm >> 1)*8) * 2);

    #pragma unroll
    for (int kk = 0; kk < 8; kk++) {
        u32 a0, a1, a2, a3;
        ldsm4(a0, a1, a2, a3, a_base + (u32)(kk*32));
        #pragma unroll
        for (int j = 0; j < 4; j++) {
            u32 b0, b1, b2, b3;
            ldsm4t(b0, b1, b2, b3, b_base + (u32)(kk*4352 + j*32));
            mma16816(acc[2*j],     a0, a1, a2, a3, b0, b1);
            mma16816(acc[2*j + 1], a0, a1, a2, a3, b2, b3);
        }
    }

    #pragma unroll
    for (int j = 0; j < 8; j++) {
        int col = wn + j*8 + 2*qt;
        int r0 = r0g + wm + grp;
        int r1 = r0 + 8;
        float o0 = swishf(acc[j][0] + __ldg(&bias[col]));
        float o1 = swishf(acc[j][1] + __ldg(&bias[col+1]));
        float o2 = swishf(acc[j][2] + __ldg(&bias[col]));
        float o3 = swishf(acc[j][3] + __ldg(&bias[col+1]));
        *(float2*)&out[r0*128 + col] = make_float2(o0, o1);
        *(float2*)&out[r1*128 + col] = make_float2(o2, o3);
    }
}

// ---------------- fused P/Q kernel (K=160, shared A, two GEMMs) ----------------
#define PQ_SMEM (43520 + 43520 + 21504)
__global__ void __launch_bounds__(256, 2)
pq_kernel(const __half* __restrict__ WPg, const __half* __restrict__ WQg,
          const float* __restrict__ u) {
    extern __shared__ __align__(16) char smbuf[];
    __half* WPs = (__half*)smbuf;                     // 160 x 136
    __half* WQs = (__half*)(smbuf + 43520);           // 160 x 136
    __half* Ah  = (__half*)(smbuf + 87040);           // 64 x 168
    const int PA = 168;

    int tid = threadIdx.x;
    int r0g = blockIdx.x * 64;

    for (int i = tid; i < 160*16; i += 256) {
        int r = i >> 4;
        int c8 = (i & 15) << 3;
        *(uint4*)&WPs[r*136 + c8] = *(const uint4*)&WPg[r*128 + c8];
        *(uint4*)&WQs[r*136 + c8] = *(const uint4*)&WQg[r*128 + c8];
    }
    for (int i = tid; i < 64*32; i += 256) {
        int r  = i >> 5;
        int k4 = (i & 31) << 2;
        float4 v = *(const float4*)&g_h[(r0g + r)*128 + k4];
        __half2* dst = (__half2*)&Ah[r*PA + k4];
        dst[0] = __floats2half2_rn(v.x, v.y);
        dst[1] = __floats2half2_rn(v.z, v.w);
    }
    for (int i = tid; i < 64*32; i += 256) {
        int r = i >> 5;
        int c = 128 + (i & 31);
        int row = r0g + r;
        float v;
        if (c < 153)       v = u[row*25 + (c - 128)];
        else if (c == 153) v = g_px[row];
        else if (c == 154) v = g_pt[row];
        else if (c == 155) v = 1.f;
        else               v = 0.f;
        Ah[r*PA + c] = __float2half(v);
    }
    __syncthreads();

    int w = tid >> 5;
    int lane = tid & 31;
    int wm = (w & 3) * 16;
    int wn = (w >> 2) * 64;
    int grp = lane >> 2;
    int qt  = lane & 3;
    int lr = lane & 7;
    int lm = lane >> 3;

    float accP[8][4], accQ[8][4];
    #pragma unroll
    for (int j = 0; j < 8; j++) {
        #pragma unroll
        for (int i = 0; i < 4; i++) { accP[j][i] = 0.f; accQ[j][i] = 0.f; }
    }

    u32 a_base  = smem_u32(Ah)  + (u32)(((wm + (lm & 1)*8 + lr)*PA + (lm >> 1)*8) * 2);
    u32 bP_base = smem_u32(WPs) + (u32)((((lm & 1)*8 + lr)*136 + wn + (lm >> 1)*8) * 2);
    u32 bQ_base = smem_u32(WQs) + (u32)((((lm & 1)*8 + lr)*136 + wn + (lm >> 1)*8) * 2);

    #pragma unroll
    for (int kk = 0; kk < 10; kk++) {
        u32 a0, a1, a2, a3;
        ldsm4(a0, a1, a2, a3, a_base + (u32)(kk*32));
        #pragma unroll
        for (int j = 0; j < 4; j++) {
            u32 b0, b1, b2, b3;
            ldsm4t(b0, b1, b2, b3, bP_base + (u32)(kk*4352 + j*32));
            mma16816(accP[2*j],     a0, a1, a2, a3, b0, b1);
            mma16816(accP[2*j + 1], a0, a1, a2, a3, b2, b3);
        }
        #pragma unroll
        for (int j = 0; j < 4; j++) {
            u32 b0, b1, b2, b3;
            ldsm4t(b0, b1, b2, b3, bQ_base + (u32)(kk*4352 + j*32));
            mma16816(accQ[2*j],     a0, a1, a2, a3, b0, b1);
            mma16816(accQ[2*j + 1], a0, a1, a2, a3, b2, b3);
        }
    }

    #pragma unroll
    for (int j = 0; j < 8; j++) {
        int col = wn + j*8 + 2*qt;
        int r0 = r0g + wm + grp;
        int r1 = r0 + 8;
        *(__half2*)&g_Ph[r0*128 + col] = __floats2half2_rn(accP[j][0], accP[j][1]);
        *(__half2*)&g_Ph[r1*128 + col] = __floats2half2_rn(accP[j][2], accP[j][3]);
        *(__half2*)&g_Qh[r0*128 + col] = __floats2half2_rn(accQ[j][0], accQ[j][1]);
        *(__half2*)&g_Qh[r1*128 + col] = __floats2half2_rn(accQ[j][2], accQ[j][3]);
    }
}

// ---------------- fused update kernel (two chained GEMMs) ----------------
#define UPD_SMEM 103424
__global__ void __launch_bounds__(256, 2)
update_kernel(const __half* __restrict__ Wu1h, const float* __restrict__ wx,
              const float* __restrict__ bu1,
              const __half* __restrict__ Wu2h, const float* __restrict__ bu2) {
    extern __shared__ __align__(16) char smbuf[];
    __half* Wh1 = (__half*)smbuf;                      // 256 x 136 (phase 1)
    __half* Ah  = (__half*)(smbuf + 69632);            // 64 x 264  (phase 1)
    __half* Wh2 = (__half*)smbuf;                      // 128 x 136 (phase 2)
    __half* Hh  = (__half*)(smbuf + 34816);            // 64 x 136  (phase 2)
    const int PA = 264;

    int tid = threadIdx.x;
    int r0g = blockIdx.x * 64;

    for (int i = tid; i < 256*16; i += 256) {
        int r = i >> 4;
        int c8 = (i & 15) << 3;
        *(uint4*)&Wh1[r*136 + c8] = *(const uint4*)&Wu1h[r*128 + c8];
    }
    for (int i = tid; i < 64*64; i += 256) {
        int r  = i >> 6;
        int k4 = (i & 63) << 2;
        int row = r0g + r;
        float4 v;
        if (k4 < 128) {
            v = *(const float4*)&g_h[row*128 + k4];
        } else {
            v = *(const float4*)&g_agg[row*128 + (k4 - 128)];
            float s = g_inv[row];
            v.x *= s; v.y *= s; v.z *= s; v.w *= s;
        }
        __half2* dst = (__half2*)&Ah[r*PA + k4];
        dst[0] = __floats2half2_rn(v.x, v.y);
        dst[1] = __floats2half2_rn(v.z, v.w);
    }
    __syncthreads();

    int w = tid >> 5;
    int lane = tid & 31;
    int wm = (w & 3) * 16;
    int wn = (w >> 2) * 64;
    int grp = lane >> 2;
    int qt  = lane & 3;
    int lr = lane & 7;
    int lm = lane >> 3;

    float acc[8][4];
    #pragma unroll
    for (int j = 0; j < 8; j++) {
        #pragma unroll
        for (int i = 0; i < 4; i++) acc[j][i] = 0.f;
    }

    u32 a_base = smem_u32(Ah)  + (u32)(((wm + (lm & 1)*8 + lr)*PA + (lm >> 1)*8) * 2);
    u32 b_base = smem_u32(Wh1) + (u32)((((lm & 1)*8 + lr)*136 + wn + (lm >> 1)*8) * 2);

    #pragma unroll
    for (int kk = 0; kk < 16; kk++) {
        u32 a0, a1, a2, a3;
        ldsm4(a0, a1, a2, a3, a_base + (u32)(kk*32));
        #pragma unroll
        for (int j = 0; j < 4; j++) {
            u32 b0, b1, b2, b3;
            ldsm4t(b0, b1, b2, b3, b_base + (u32)(kk*4352 + j*32));
            mma16816(acc[2*j],     a0, a1, a2, a3, b0, b1);
            mma16816(acc[2*j + 1], a0, a1, a2, a3, b2, b3);
        }
    }
    __syncthreads();

    {
        int er0 = wm + grp;
        int er1 = er0 + 8;
        float pt0 = g_pt[r0g + er0], pt1 = g_pt[r0g + er1];
        #pragma unroll
        for (int j = 0; j < 8; j++) {
            int col = wn + j*8 + 2*qt;
            float o0 = swishf(acc[j][0] + pt0*__ldg(&wx[col])   + __ldg(&bu1[col]));
            float o1 = swishf(acc[j][1] + pt0*__ldg(&wx[col+1]) + __ldg(&bu1[col+1]));
            float o2 = swishf(acc[j][2] + pt1*__ldg(&wx[col])   + __ldg(&bu1[col]));
            float o3 = swishf(acc[j][3] + pt1*__ldg(&wx[col+1]) + __ldg(&bu1[col+1]));
            *(__half2*)&Hh[er0*136 + col] = __floats2half2_rn(o0, o1);
            *(__half2*)&Hh[er1*136 + col] = __floats2half2_rn(o2, o3);
        }
    }
    for (int i = tid; i < 128*16; i += 256) {
        int r = i >> 4;
        int c8 = (i & 15) << 3;
        *(uint4*)&Wh2[r*136 + c8] = *(const uint4*)&Wu2h[r*128 + c8];
    }
    __syncthreads();

    #pragma unroll
    for (int j = 0; j < 8; j++) {
        #pragma unroll
        for (int i = 0; i < 4; i++) acc[j][i] = 0.f;
    }
    u32 a2_base = smem_u32(Hh)  + (u32)(((wm + (lm & 1)*8 + lr)*136 + (lm >> 1)*8) * 2);
    u32 b2_base = smem_u32(Wh2) + (u32)((((lm & 1)*8 + lr)*136 + wn + (lm >> 1)*8) * 2);
    #pragma unroll
    for (int kk = 0; kk < 8; kk++) {
        u32 a0, a1, a2, a3;
        ldsm4(a0, a1, a2, a3, a2_base + (u32)(kk*32));
        #pragma unroll
        for (int j = 0; j < 4; j++) {
            u32 b0, b1, b2, b3;
            ldsm4t(b0, b1, b2, b3, b2_base + (u32)(kk*4352 + j*32));
            mma16816(acc[2*j],     a0, a1, a2, a3, b0, b1);
            mma16816(acc[2*j + 1], a0, a1, a2, a3, b2, b3);
        }
    }

    #pragma unroll
    for (int j = 0; j < 8; j++) {
        int col = wn + j*8 + 2*qt;
        int r0 = r0g + wm + grp;
        int r1 = r0 + 8;
        float2 h0 = *(float2*)&g_h[r0*128 + col];
        float2 h1 = *(float2*)&g_h[r1*128 + col];
        h0.x += swishf(acc[j][0] + __ldg(&bu2[col]));
        h0.y += swishf(acc[j][1] + __ldg(&bu2[col+1]));
        h1.x += swishf(acc[j][2] + __ldg(&bu2[col]));
        h1.y += swishf(acc[j][3] + __ldg(&bu2[col+1]));
        *(float2*)&g_h[r0*128 + col] = h0;
        *(float2*)&g_h[r1*128 + col] = h1;
    }
}

// ---------------- fused edge kernel (R10-proven) ----------------
#define EDGE_SMEM (34816 + 17408 + 512)
#define EDGE_GRID 512
__global__ void edge_kernel(const int* __restrict__ eidx,
                            const __half* __restrict__ Whg,
                            const float* __restrict__ bm2l) {
    extern __shared__ __align__(16) char smbuf[];
    __half* Wh = (__half*)smbuf;                       // 128 x 136
    __half* Mh = (__half*)(smbuf + 34816);             // 64 x 136
    int*    st = (int*)(smbuf + 34816 + 17408);
    int*    se = st + 64;

    int tid = threadIdx.x;

    for (int i = tid; i < 128*16; i += 256) {
        int r = i >> 4;
        int c8 = (i & 15) << 3;
        uint4 v = *(const uint4*)&Whg[r*128 + c8];
        *(uint4*)&Wh[r*136 + c8] = v;
    }

    int w = tid >> 5;
    int lane = tid & 31;
    int wm = (w & 3) * 16;
    int wn = (w >> 2) * 64;
    int grp = lane >> 2;
    int qt  = lane & 3;
    int lr = lane & 7;
    int lm = lane >> 3;

    u32 a_base = smem_u32(Mh) + (u32)(((wm + (lm & 1)*8 + lr)*136 + (lm >> 1)*8) * 2);
    u32 b_base = smem_u32(Wh) + (u32)((((lm & 1)*8 + lr)*136 + wn + (lm >> 1)*8) * 2);

    for (int tile = blockIdx.x; tile < EE/64; tile += EDGE_GRID) {
        int e0 = tile * 64;
        __syncthreads();
        if (tid < 64) {
            se[tid] = eidx[e0 + tid];
            st[tid] = eidx[EE + e0 + tid];
        }
        __syncthreads();

        for (int i = tid; i < 64*16; i += 256) {
            int e = i >> 4;
            int c8 = (i & 15) << 3;
            uint4 pv = *(const uint4*)&g_Ph[st[e]*128 + c8];
            uint4 qv = *(const uint4*)&g_Qh[se[e]*128 + c8];
            __half2* ph = (__half2*)&pv;
            __half2* qh = (__half2*)&qv;
            uint4 ov;
            __half2* oh = (__half2*)&ov;
            #pragma unroll
            for (int k2 = 0; k2 < 4; k2++) {
                float2 p2 = __half22float2(ph[k2]);
                float2 q2 = __half22float2(qh[k2]);
                oh[k2] = __floats2half2_rn(swishf(p2.x + q2.x), swishf(p2.y + q2.y));
            }
            *(uint4*)&Mh[e*136 + c8] = ov;
        }
        __syncthreads();

        float acc[8][4];
        #pragma unroll
        for (int j = 0; j < 8; j++) {
            #pragma unroll
            for (int i = 0; i < 4; i++) acc[j][i] = 0.f;
        }

        #pragma unroll
        for (int kk = 0; kk < 8; kk++) {
            u32 a0, a1, a2, a3;
            ldsm4(a0, a1, a2, a3, a_base + (u32)(kk*32));
            #pragma unroll
            for (int j = 0; j < 4; j++) {
                u32 b0, b1, b2, b3;
                ldsm4t(b0, b1, b2, b3, b_base + (u32)(kk*4352 + j*32));
                mma16816(acc[2*j],     a0, a1, a2, a3, b0, b1);
                mma16816(acc[2*j + 1], a0, a1, a2, a3, b2, b3);
            }
        }

        int er0 = wm + grp;
        int er1 = er0 + 8;
        int t0 = st[er0];
        int t1 = st[er1];
        #pragma unroll
        for (int j = 0; j < 8; j++) {
            int col = wn + j*8 + 2*qt;
            float b0v = __ldg(&bm2l[col]);
            float b1v = __ldg(&bm2l[col + 1]);
            atomicAdd(&g_agg[t0*128 + col],     swishf(acc[j][0] + b0v));
            atomicAdd(&g_agg[t0*128 + col + 1], swishf(acc[j][1] + b1v));
            atomicAdd(&g_agg[t1*128 + col],     swishf(acc[j][2] + b0v));
            atomicAdd(&g_agg[t1*128 + col + 1], swishf(acc[j][3] + b1v));
        }
    }
}

// ---------------- per-batch norm ----------------
__global__ void norm_reduce(const int* __restrict__ batch) {
    int c = threadIdx.x;
    int base = blockIdx.x * 128;
    float s = 0.f, q = 0.f;
    for (int r = 0; r < 128; r++) {
        float v = g_h[(base + r)*128 + c];
        s += v;
        q += v*v;
    }
    int b = batch[base];
    atomicAdd(&g_meanb[b*128 + c], s);
    atomicAdd(&g_sqb[b*128 + c], q);
}

__global__ void norm_apply(const int* __restrict__ batch) {
    int i = blockIdx.x * 256 + threadIdx.x;
    int node = i >> 7;
    int c = i & 127;
    int b = batch[node];
    float gi = 1.f / g_gcnt[b];
    float m = g_meanb[b*128 + c] * gi;
    float var = g_sqb[b*128 + c] * gi - m*m;
    g_h[i] = (g_h[i] - m) * rsqrtf(var + 1e-5f);
}

// ---------------- conv decoder ----------------
__global__ void decoder(const float* __restrict__ u,
                        const float* __restrict__ Wc1, const float* __restrict__ bc1,
                        const float* __restrict__ Wc2, const float* __restrict__ bc2,
                        float* __restrict__ out) {
    __shared__ float hr[128];
    __shared__ float c1[8*38];
    int n = blockIdx.x;
    int tid = threadIdx.x;
    for (int i = tid; i < 128; i += 64) hr[i] = g_h[n*128 + i];
    __syncthreads();
    for (int i = tid; i < 8*38; i += 64) {
        int ch = i / 38;
        int p = i % 38;
        float a = __ldg(&bc1[ch]);
        #pragma unroll
        for (int k = 0; k < 16; k++) a += hr[3*p + k] * __ldg(&Wc1[ch*16 + k]);
        c1[i] = swishf(a);
    }
    __syncthreads();
    if (tid < 25) {
        float a = __ldg(&bc2[0]);
        #pragma unroll
        for (int c = 0; c < 8; c++) {
            #pragma unroll
            for (int k = 0; k < 14; k++)
                a += c1[c*38 + tid + k] * __ldg(&Wc2[c*14 + k]);
        }
        float dt = 4.0f / 250.0f;
        out[n*25 + tid] = u[n*25 + 24] + (float)(tid + 1) * dt * a;
    }
}

// ---------------- host ----------------
extern "C" void kernel_launch(void* const* d_in, const int* in_sizes, int n_in,
                              void* d_out, int out_size) {
    const float* u     = (const float*)d_in[0];
    const float* pos   = (const float*)d_in[1];
    const int*   eidx  = (const int*)d_in[2];
    const int*   batch = (const int*)d_in[3];
    const float* We1 = (const float*)d_in[4];
    const float* be1 = (const float*)d_in[5];
    const float* We2 = (const float*)d_in[6];
    const float* be2 = (const float*)d_in[7];
    const float* Wm1 = (const float*)d_in[8];
    const float* bm1 = (const float*)d_in[9];
    const float* Wm2 = (const float*)d_in[10];
    const float* bm2 = (const float*)d_in[11];
    const float* Wu1 = (const float*)d_in[12];
    const float* bu1 = (const float*)d_in[13];
    const float* Wu2 = (const float*)d_in[14];
    const float* bu2 = (const float*)d_in[15];
    const float* Wc1 = (const float*)d_in[16];
    const float* bc1 = (const float*)d_in[17];
    const float* Wc2 = (const float*)d_in[18];
    const float* bc2 = (const float*)d_in[19];
    float* out = (float*)d_out;

    void *a_h = 0, *a_t1 = 0, *a_wm2h = 0, *a_wph = 0, *a_wqh = 0, *a_wu1h = 0, *a_wu2h = 0;
    cudaGetSymbolAddress(&a_h,    g_h);
    cudaGetSymbolAddress(&a_t1,   g_t1);
    cudaGetSymbolAddress(&a_wm2h, g_Wm2h);
    cudaGetSymbolAddress(&a_wph,  g_WPh);
    cudaGetSymbolAddress(&a_wqh,  g_WQh);
    cudaGetSymbolAddress(&a_wu1h, g_Wu1h);
    cudaGetSymbolAddress(&a_wu2h, g_Wu2h);
    float*  h    = (float*)a_h;
    float*  t1   = (float*)a_t1;
    __half* Wm2h = (__half*)a_wm2h;
    __half* WPh  = (__half*)a_wph;
    __half* WQh  = (__half*)a_wqh;
    __half* Wu1h = (__half*)a_wu1h;
    __half* Wu2h = (__half*)a_wu2h;

    int MLP_SMEM_128 = (128*136 + 64*136) * 2;
    cudaFuncSetAttribute(mlp16, cudaFuncAttributeMaxDynamicSharedMemorySize, MLP_SMEM_128);
    cudaFuncSetAttribute(pq_kernel, cudaFuncAttributeMaxDynamicSharedMemorySize, PQ_SMEM);
    cudaFuncSetAttribute(update_kernel, cudaFuncAttributeMaxDynamicSharedMemorySize, UPD_SMEM);
    cudaFuncSetAttribute(edge_kernel, cudaFuncAttributeMaxDynamicSharedMemorySize, EDGE_SMEM);

    convert_wm2<<<(LL*HH*HH/2)/256, 256>>>(Wm2);
    build_pq_w<<<(LL*160*128 + 255)/256, 256>>>(Wm1, bm1);
    build_u_w<<<(LL*256*128 + 255)/256, 256>>>(Wu1, Wu2);
    zero_prep<<<NN/256, 256>>>();
    prep_node<<<NN/256, 256>>>(pos, batch);
    prep_edge<<<EE/256, 256>>>(eidx);
    fin_cnt<<<NN/256, 256>>>();

    encoder1<<<NN, 128>>>(u, We1, be1);
    mlp16<<<NN/64, 256, MLP_SMEM_128>>>(t1, We2, be2, h);

    for (int l = 0; l < LL; l++) {
        pq_kernel<<<NN/64, 256, PQ_SMEM>>>(WPh + (size_t)l*160*128, WQh + (size_t)l*160*128, u);

        zero_agg<<<(NN*HH/4)/256, 256>>>();
        edge_kernel<<<EDGE_GRID, 256, EDGE_SMEM>>>(eidx, Wm2h + (size_t)l*HH*HH, bm2 + l*128);

        update_kernel<<<NN/64, 256, UPD_SMEM>>>(Wu1h + (size_t)l*256*128,
                                                Wu1 + (size_t)l*257*128 + 256*128,
                                                bu1 + l*128,
                                                Wu2h + (size_t)l*128*128,
                                                bu2 + l*128);

        zero_stats<<<(BB*HH + 255)/256, 256>>>();
        norm_reduce<<<NN/128, 128>>>(batch);
        norm_apply<<<(NN*HH)/256, 256>>>(batch);
    }

    decoder<<<NN, 64>>>(u, Wc1, bc1, Wc2, bc2, out);
}

// round 14
// speedup vs baseline: 1.3465x; 1.0828x over previous
#include <cuda_runtime.h>
#include <cuda_fp16.h>
#include <cstdint>
#include <math.h>

typedef unsigned int u32;

#define NN 32768
#define EE 262144
#define BB 8
#define HH 128
#define LL 6

// ---------------- scratch (device globals; no allocation) ----------------
__device__ __align__(16) float g_h[NN*HH];
__device__ __align__(16) float g_t1[NN*HH];
__device__ __align__(16) __half g_Ph[NN*HH];
__device__ __align__(16) __half g_Qh[NN*HH];
__device__ __align__(16) float g_agg[NN*HH];
__device__ __align__(16) __half g_Wm2h[LL*HH*HH];
__device__ __align__(16) __half g_WPh[LL*160*128];
__device__ __align__(16) __half g_WQh[LL*160*128];
__device__ __align__(16) __half g_Wu1h[LL*256*128];
__device__ __align__(16) __half g_Wu2h[LL*128*128];
__device__ float g_px[NN];
__device__ float g_pt[NN];
__device__ int   g_icnt[NN];
__device__ float g_inv[NN];
__device__ __align__(16) float g_meanb[BB*HH];
__device__ __align__(16) float g_sqb[BB*HH];
__device__ __align__(16) float g_mean[BB*HH];
__device__ __align__(16) float g_rstd[BB*HH];
__device__ float g_gcnt[BB];

__device__ __forceinline__ float swishf(float x) {
    return x / (1.f + __expf(-x));
}

__device__ __forceinline__ u32 smem_u32(const void* p) {
    return (u32)__cvta_generic_to_shared(p);
}

__device__ __forceinline__ void ldsm4(u32& r0, u32& r1, u32& r2, u32& r3, u32 a) {
    asm volatile("ldmatrix.sync.aligned.m8n8.x4.shared.b16 {%0,%1,%2,%3}, [%4];"
                 : "=r"(r0), "=r"(r1), "=r"(r2), "=r"(r3) : "r"(a));
}

__device__ __forceinline__ void ldsm4t(u32& r0, u32& r1, u32& r2, u32& r3, u32 a) {
    asm volatile("ldmatrix.sync.aligned.m8n8.x4.trans.shared.b16 {%0,%1,%2,%3}, [%4];"
                 : "=r"(r0), "=r"(r1), "=r"(r2), "=r"(r3) : "r"(a));
}

__device__ __forceinline__ void mma16816(float* c, u32 a0, u32 a1, u32 a2, u32 a3,
                                         u32 b0, u32 b1) {
    asm volatile("mma.sync.aligned.m16n8k16.row.col.f32.f16.f16.f32 "
                 "{%0,%1,%2,%3}, {%4,%5,%6,%7}, {%8,%9}, {%0,%1,%2,%3};"
                 : "+f"(c[0]), "+f"(c[1]), "+f"(c[2]), "+f"(c[3])
                 : "r"(a0), "r"(a1), "r"(a2), "r"(a3), "r"(b0), "r"(b1));
}

// ---------------- zero / prep ----------------
__global__ void zero_prep() {
    int i = blockIdx.x * 256 + threadIdx.x;
    if (i < NN) g_icnt[i] = 0;
    if (i < BB) g_gcnt[i] = 0.f;
}

__global__ void init_stats() {
    int i = threadIdx.x + blockIdx.x * 256;
    if (i < BB*HH) {
        g_mean[i] = 0.f;
        g_rstd[i] = 1.f;
        g_meanb[i] = 0.f;
        g_sqb[i]  = 0.f;
    }
}

// finalize stats for the layer just finished; re-zero accumulators
__global__ void fin_stats() {
    int i = threadIdx.x + blockIdx.x * 256;
    if (i < BB*HH) {
        int b = i >> 7;
        float gi = 1.f / g_gcnt[b];
        float m = g_meanb[i] * gi;
        float var = g_sqb[i] * gi - m*m;
        g_mean[i] = m;
        g_rstd[i] = rsqrtf(var + 1e-5f);
        g_meanb[i] = 0.f;
        g_sqb[i]  = 0.f;
    }
}

__global__ void zero_agg() {
    int i = blockIdx.x * 256 + threadIdx.x;   // over NN*HH/4
    ((float4*)g_agg)[i] = make_float4(0.f, 0.f, 0.f, 0.f);
}

__global__ void prep_node(const float* __restrict__ pos, const int* __restrict__ batch) {
    int i = blockIdx.x * 256 + threadIdx.x;
    if (i < NN) {
        g_pt[i] = pos[2*i]   * 0.25f;
        g_px[i] = pos[2*i+1] * 0.0625f;
        atomicAdd(&g_gcnt[batch[i]], 1.f);
    }
}

__global__ void prep_edge(const int* __restrict__ eidx) {
    int e = blockIdx.x * 256 + threadIdx.x;
    if (e < EE) atomicAdd(&g_icnt[eidx[EE + e]], 1);
}

__global__ void fin_cnt() {
    int i = blockIdx.x * 256 + threadIdx.x;
    if (i < NN) g_inv[i] = 1.f / (float)max(g_icnt[i], 1);
}

__global__ void convert_wm2(const float* __restrict__ Wm2) {
    int i = blockIdx.x * 256 + threadIdx.x;   // over LL*HH*HH/2
    float2 v = ((const float2*)Wm2)[i];
    ((__half2*)g_Wm2h)[i] = __floats2half2_rn(v.x, v.y);
}

// build folded P/Q weights
__global__ void build_pq_w(const float* __restrict__ Wm1, const float* __restrict__ bm1) {
    int i = blockIdx.x * 256 + threadIdx.x;   // over LL*160*128
    if (i >= LL*160*128) return;
    int l = i / (160*128);
    int r = (i / 128) % 160;
    int c = i & 127;
    const float* W = Wm1 + (size_t)l * 283 * 128;
    float p, q;
    if (r < 128)       { p = W[r*128 + c];              q = W[(128 + r)*128 + c]; }
    else if (r < 153)  { float v = W[(256 + r - 128)*128 + c]; p = v; q = -v; }
    else if (r == 153) { float v = W[281*128 + c];      p = v; q = -v; }
    else if (r == 154) { p = W[282*128 + c];            q = 0.f; }
    else if (r == 155) { p = bm1[l*128 + c];            q = 0.f; }
    else               { p = 0.f;                        q = 0.f; }
    g_WPh[i] = __float2half(p);
    g_WQh[i] = __float2half(q);
}

__global__ void build_u_w(const float* __restrict__ Wu1, const float* __restrict__ Wu2) {
    int i = blockIdx.x * 256 + threadIdx.x;   // over LL*256*128
    if (i >= LL*256*128) return;
    int l = i / (256*128);
    int rc = i % (256*128);
    g_Wu1h[i] = __float2half(Wu1[(size_t)l*257*128 + rc]);
    if (rc < 128*128) g_Wu2h[(size_t)l*128*128 + rc] = __float2half(Wu2[(size_t)l*128*128 + rc]);
}

// ---------------- encoder ----------------
__global__ void encoder1(const float* __restrict__ u, const float* __restrict__ We1,
                         const float* __restrict__ be1) {
    __shared__ float s[27];
    int n = blockIdx.x;
    int t = threadIdx.x;
    if (t < 25)       s[t]  = u[n*25 + t];
    else if (t == 25) s[25] = g_px[n];
    else if (t == 26) s[26] = g_pt[n];
    __syncthreads();
    float a = __ldg(&be1[t]);
    #pragma unroll
    for (int k = 0; k < 27; k++) a += s[k] * __ldg(&We1[k*128 + t]);
    g_t1[n*128 + t] = swishf(a);
}

// generic fp16 GEMM (encoder second layer): out = swish(A@W + b)
__global__ void mlp16(const float* __restrict__ A,
                      const float* __restrict__ W, const float* __restrict__ bias,
                      float* __restrict__ out) {
    extern __shared__ __align__(16) char smbuf[];
    __half* Wh = (__half*)smbuf;            // 128 x 136
    __half* Ah = Wh + 128*136;              // 64 x 136
    const int PA = 136;

    int tid = threadIdx.x;
    int r0g = blockIdx.x * 64;

    for (int i = tid; i < 128*32; i += 256) {
        int k = i >> 5;
        int c4 = (i & 31) << 2;
        float4 v = *(const float4*)&W[k*128 + c4];
        __half2* dst = (__half2*)&Wh[k*136 + c4];
        dst[0] = __floats2half2_rn(v.x, v.y);
        dst[1] = __floats2half2_rn(v.z, v.w);
    }
    for (int i = tid; i < 64*32; i += 256) {
        int r  = i >> 5;
        int k4 = (i & 31) << 2;
        float4 v = *(const float4*)&A[(r0g + r)*128 + k4];
        __half2* dst = (__half2*)&Ah[r*PA + k4];
        dst[0] = __floats2half2_rn(v.x, v.y);
        dst[1] = __floats2half2_rn(v.z, v.w);
    }
    __syncthreads();

    int w = tid >> 5;
    int lane = tid & 31;
    int wm = (w & 3) * 16;
    int wn = (w >> 2) * 64;
    int grp = lane >> 2;
    int qt  = lane & 3;
    int lr = lane & 7;
    int lm = lane >> 3;

    float acc[8][4];
    #pragma unroll
    for (int j = 0; j < 8; j++) {
        #pragma unroll
        for (int i = 0; i < 4; i++) acc[j][i] = 0.f;
    }

    u32 a_base = smem_u32(Ah) + (u32)(((wm + (lm & 1)*8 + lr)*PA + (lm >> 1)*8) * 2);
    u32 b_base = smem_u32(Wh) + (u32)((((lm & 1)*8 + lr)*136 + wn + (lm >> 1)*8) * 2);

    #pragma unroll
    for (int kk = 0; kk < 8; kk++) {
        u32 a0, a1, a2, a3;
        ldsm4(a0, a1, a2, a3, a_base + (u32)(kk*32));
        #pragma unroll
        for (int j = 0; j < 4; j++) {
            u32 b0, b1, b2, b3;
            ldsm4t(b0, b1, b2, b3, b_base + (u32)(kk*4352 + j*32));
            mma16816(acc[2*j],     a0, a1, a2, a3, b0, b1);
            mma16816(acc[2*j + 1], a0, a1, a2, a3, b2, b3);
        }
    }

    #pragma unroll
    for (int j = 0; j < 8; j++) {
        int col = wn + j*8 + 2*qt;
        int r0 = r0g + wm + grp;
        int r1 = r0 + 8;
        float o0 = swishf(acc[j][0] + __ldg(&bias[col]));
        float o1 = swishf(acc[j][1] + __ldg(&bias[col+1]));
        float o2 = swishf(acc[j][2] + __ldg(&bias[col]));
        float o3 = swishf(acc[j][3] + __ldg(&bias[col+1]));
        *(float2*)&out[r0*128 + col] = make_float2(o0, o1);
        *(float2*)&out[r1*128 + col] = make_float2(o2, o3);
    }
}

// ---------------- fused P/Q kernel (K=160, shared A, two GEMMs, normalized h staging) ----------------
#define PQ_SMEM (43520 + 43520 + 21504)
__global__ void __launch_bounds__(256, 2)
pq_kernel(const __half* __restrict__ WPg, const __half* __restrict__ WQg,
          const float* __restrict__ u) {
    extern __shared__ __align__(16) char smbuf[];
    __half* WPs = (__half*)smbuf;                     // 160 x 136
    __half* WQs = (__half*)(smbuf + 43520);           // 160 x 136
    __half* Ah  = (__half*)(smbuf + 87040);           // 64 x 168
    const int PA = 168;

    int tid = threadIdx.x;
    int r0g = blockIdx.x * 64;
    int bseg = r0g >> 12;

    for (int i = tid; i < 160*16; i += 256) {
        int r = i >> 4;
        int c8 = (i & 15) << 3;
        *(uint4*)&WPs[r*136 + c8] = *(const uint4*)&WPg[r*128 + c8];
        *(uint4*)&WQs[r*136 + c8] = *(const uint4*)&WQg[r*128 + c8];
    }
    for (int i = tid; i < 64*32; i += 256) {
        int r  = i >> 5;
        int k4 = (i & 31) << 2;
        float4 v = *(const float4*)&g_h[(r0g + r)*128 + k4];
        float4 m = *(const float4*)&g_mean[bseg*128 + k4];
        float4 rs = *(const float4*)&g_rstd[bseg*128 + k4];
        v.x = (v.x - m.x)*rs.x;
        v.y = (v.y - m.y)*rs.y;
        v.z = (v.z - m.z)*rs.z;
        v.w = (v.w - m.w)*rs.w;
        __half2* dst = (__half2*)&Ah[r*PA + k4];
        dst[0] = __floats2half2_rn(v.x, v.y);
        dst[1] = __floats2half2_rn(v.z, v.w);
    }
    for (int i = tid; i < 64*32; i += 256) {
        int r = i >> 5;
        int c = 128 + (i & 31);
        int row = r0g + r;
        float v;
        if (c < 153)       v = u[row*25 + (c - 128)];
        else if (c == 153) v = g_px[row];
        else if (c == 154) v = g_pt[row];
        else if (c == 155) v = 1.f;
        else               v = 0.f;
        Ah[r*PA + c] = __float2half(v);
    }
    __syncthreads();

    int w = tid >> 5;
    int lane = tid & 31;
    int wm = (w & 3) * 16;
    int wn = (w >> 2) * 64;
    int grp = lane >> 2;
    int qt  = lane & 3;
    int lr = lane & 7;
    int lm = lane >> 3;

    float accP[8][4], accQ[8][4];
    #pragma unroll
    for (int j = 0; j < 8; j++) {
        #pragma unroll
        for (int i = 0; i < 4; i++) { accP[j][i] = 0.f; accQ[j][i] = 0.f; }
    }

    u32 a_base  = smem_u32(Ah)  + (u32)(((wm + (lm & 1)*8 + lr)*PA + (lm >> 1)*8) * 2);
    u32 bP_base = smem_u32(WPs) + (u32)((((lm & 1)*8 + lr)*136 + wn + (lm >> 1)*8) * 2);
    u32 bQ_base = smem_u32(WQs) + (u32)((((lm & 1)*8 + lr)*136 + wn + (lm >> 1)*8) * 2);

    #pragma unroll
    for (int kk = 0; kk < 10; kk++) {
        u32 a0, a1, a2, a3;
        ldsm4(a0, a1, a2, a3, a_base + (u32)(kk*32));
        #pragma unroll
        for (int j = 0; j < 4; j++) {
            u32 b0, b1, b2, b3;
            ldsm4t(b0, b1, b2, b3, bP_base + (u32)(kk*4352 + j*32));
            mma16816(accP[2*j],     a0, a1, a2, a3, b0, b1);
            mma16816(accP[2*j + 1], a0, a1, a2, a3, b2, b3);
        }
        #pragma unroll
        for (int j = 0; j < 4; j++) {
            u32 b0, b1, b2, b3;
            ldsm4t(b0, b1, b2, b3, bQ_base + (u32)(kk*4352 + j*32));
            mma16816(accQ[2*j],     a0, a1, a2, a3, b0, b1);
            mma16816(accQ[2*j + 1], a0, a1, a2, a3, b2, b3);
        }
    }

    #pragma unroll
    for (int j = 0; j < 8; j++) {
        int col = wn + j*8 + 2*qt;
        int r0 = r0g + wm + grp;
        int r1 = r0 + 8;
        *(__half2*)&g_Ph[r0*128 + col] = __floats2half2_rn(accP[j][0], accP[j][1]);
        *(__half2*)&g_Ph[r1*128 + col] = __floats2half2_rn(accP[j][2], accP[j][3]);
        *(__half2*)&g_Qh[r0*128 + col] = __floats2half2_rn(accQ[j][0], accQ[j][1]);
        *(__half2*)&g_Qh[r1*128 + col] = __floats2half2_rn(accQ[j][2], accQ[j][3]);
    }
}

// ---------------- fused update kernel (two chained GEMMs + norm-stat reduction) ----------------
// phase1: Wh1 256x136 (69632) | Ah 64x264 (33792)  = 103424
// phase2: Wh2 128x136 (34816) | Hh 64x136 (17408) | Hs 64x128 f32 (32768) | ps 256 f32 | qs 256 f32 = 89088
#define UPD_SMEM 103424
__global__ void __launch_bounds__(256, 2)
update_kernel(const __half* __restrict__ Wu1h, const float* __restrict__ wx,
              const float* __restrict__ bu1,
              const __half* __restrict__ Wu2h, const float* __restrict__ bu2) {
    extern __shared__ __align__(16) char smbuf[];
    __half* Wh1 = (__half*)smbuf;                      // 256 x 136 (phase 1)
    __half* Ah  = (__half*)(smbuf + 69632);            // 64 x 264  (phase 1)
    __half* Wh2 = (__half*)smbuf;                      // 128 x 136 (phase 2)
    __half* Hh  = (__half*)(smbuf + 34816);            // 64 x 136  (phase 2)
    float*  Hs  = (float*)(smbuf + 52224);             // 64 x 128  (phase 2)
    float*  ps  = (float*)(smbuf + 84992);             // 256
    float*  qs  = (float*)(smbuf + 86016);             // 256
    const int PA = 264;

    int tid = threadIdx.x;
    int r0g = blockIdx.x * 64;
    int bseg = r0g >> 12;

    for (int i = tid; i < 256*16; i += 256) {
        int r = i >> 4;
        int c8 = (i & 15) << 3;
        *(uint4*)&Wh1[r*136 + c8] = *(const uint4*)&Wu1h[r*128 + c8];
    }
    for (int i = tid; i < 64*64; i += 256) {
        int r  = i >> 6;
        int k4 = (i & 63) << 2;
        int row = r0g + r;
        float4 v;
        if (k4 < 128) {
            v = *(const float4*)&g_h[row*128 + k4];
            float4 m = *(const float4*)&g_mean[bseg*128 + k4];
            float4 rs = *(const float4*)&g_rstd[bseg*128 + k4];
            v.x = (v.x - m.x)*rs.x;
            v.y = (v.y - m.y)*rs.y;
            v.z = (v.z - m.z)*rs.z;
            v.w = (v.w - m.w)*rs.w;
        } else {
            v = *(const float4*)&g_agg[row*128 + (k4 - 128)];
            float s = g_inv[row];
            v.x *= s; v.y *= s; v.z *= s; v.w *= s;
        }
        __half2* dst = (__half2*)&Ah[r*PA + k4];
        dst[0] = __floats2half2_rn(v.x, v.y);
        dst[1] = __floats2half2_rn(v.z, v.w);
    }
    __syncthreads();

    int w = tid >> 5;
    int lane = tid & 31;
    int wm = (w & 3) * 16;
    int wn = (w >> 2) * 64;
    int grp = lane >> 2;
    int qt  = lane & 3;
    int lr = lane & 7;
    int lm = lane >> 3;

    float acc[8][4];
    #pragma unroll
    for (int j = 0; j < 8; j++) {
        #pragma unroll
        for (int i = 0; i < 4; i++) acc[j][i] = 0.f;
    }

    u32 a_base = smem_u32(Ah)  + (u32)(((wm + (lm & 1)*8 + lr)*PA + (lm >> 1)*8) * 2);
    u32 b_base = smem_u32(Wh1) + (u32)((((lm & 1)*8 + lr)*136 + wn + (lm >> 1)*8) * 2);

    #pragma unroll
    for (int kk = 0; kk < 16; kk++) {
        u32 a0, a1, a2, a3;
        ldsm4(a0, a1, a2, a3, a_base + (u32)(kk*32));
        #pragma unroll
        for (int j = 0; j < 4; j++) {
            u32 b0, b1, b2, b3;
            ldsm4t(b0, b1, b2, b3, b_base + (u32)(kk*4352 + j*32));
            mma16816(acc[2*j],     a0, a1, a2, a3, b0, b1);
            mma16816(acc[2*j + 1], a0, a1, a2, a3, b2, b3);
        }
    }
    __syncthreads();

    {
        int er0 = wm + grp;
        int er1 = er0 + 8;
        float pt0 = g_pt[r0g + er0], pt1 = g_pt[r0g + er1];
        #pragma unroll
        for (int j = 0; j < 8; j++) {
            int col = wn + j*8 + 2*qt;
            float o0 = swishf(acc[j][0] + pt0*__ldg(&wx[col])   + __ldg(&bu1[col]));
            float o1 = swishf(acc[j][1] + pt0*__ldg(&wx[col+1]) + __ldg(&bu1[col+1]));
            float o2 = swishf(acc[j][2] + pt1*__ldg(&wx[col])   + __ldg(&bu1[col]));
            float o3 = swishf(acc[j][3] + pt1*__ldg(&wx[col+1]) + __ldg(&bu1[col+1]));
            *(__half2*)&Hh[er0*136 + col] = __floats2half2_rn(o0, o1);
            *(__half2*)&Hh[er1*136 + col] = __floats2half2_rn(o2, o3);
        }
    }
    for (int i = tid; i < 128*16; i += 256) {
        int r = i >> 4;
        int c8 = (i & 15) << 3;
        *(uint4*)&Wh2[r*136 + c8] = *(const uint4*)&Wu2h[r*128 + c8];
    }
    __syncthreads();

    #pragma unroll
    for (int j = 0; j < 8; j++) {
        #pragma unroll
        for (int i = 0; i < 4; i++) acc[j][i] = 0.f;
    }
    u32 a2_base = smem_u32(Hh)  + (u32)(((wm + (lm & 1)*8 + lr)*136 + (lm >> 1)*8) * 2);
    u32 b2_base = smem_u32(Wh2) + (u32)((((lm & 1)*8 + lr)*136 + wn + (lm >> 1)*8) * 2);
    #pragma unroll
    for (int kk = 0; kk < 8; kk++) {
        u32 a0, a1, a2, a3;
        ldsm4(a0, a1, a2, a3, a2_base + (u32)(kk*32));
        #pragma unroll
        for (int j = 0; j < 4; j++) {
            u32 b0, b1, b2, b3;
            ldsm4t(b0, b1, b2, b3, b2_base + (u32)(kk*4352 + j*32));
            mma16816(acc[2*j],     a0, a1, a2, a3, b0, b1);
            mma16816(acc[2*j + 1], a0, a1, a2, a3, b2, b3);
        }
    }

    // epilogue2: h_new = norm(h_old) + swish(acc + bu2); write g_h and Hs
    #pragma unroll
    for (int j = 0; j < 8; j++) {
        int col = wn + j*8 + 2*qt;
        int r0 = r0g + wm + grp;
        int r1 = r0 + 8;
        float m0 = __ldg(&g_mean[bseg*128 + col]);
        float m1 = __ldg(&g_mean[bseg*128 + col + 1]);
        float s0 = __ldg(&g_rstd[bseg*128 + col]);
        float s1 = __ldg(&g_rstd[bseg*128 + col + 1]);
        float2 h0 = *(float2*)&g_h[r0*128 + col];
        float2 h1 = *(float2*)&g_h[r1*128 + col];
        h0.x = (h0.x - m0)*s0 + swishf(acc[j][0] + __ldg(&bu2[col]));
        h0.y = (h0.y - m1)*s1 + swishf(acc[j][1] + __ldg(&bu2[col+1]));
        h1.x = (h1.x - m0)*s0 + swishf(acc[j][2] + __ldg(&bu2[col]));
        h1.y = (h1.y - m1)*s1 + swishf(acc[j][3] + __ldg(&bu2[col+1]));
        *(float2*)&g_h[r0*128 + col] = h0;
        *(float2*)&g_h[r1*128 + col] = h1;
        *(float2*)&Hs[(wm + grp)*128 + col] = h0;
        *(float2*)&Hs[(wm + grp + 8)*128 + col] = h1;
    }
    __syncthreads();

    // block-level norm-stat reduction over 64 rows
    {
        int col = tid & 127;
        int half = tid >> 7;
        float s = 0.f, q = 0.f;
        #pragma unroll 8
        for (int r = half*32; r < half*32 + 32; r++) {
            float v = Hs[r*128 + col];
            s += v;
            q += v*v;
        }
        ps[tid] = s;
        qs[tid] = q;
    }
    __syncthreads();
    if (tid < 128) {
        float S = ps[tid] + ps[tid + 128];
        float Q = qs[tid] + qs[tid + 128];
        atomicAdd(&g_meanb[bseg*128 + tid], S);
        atomicAdd(&g_sqb[bseg*128 + tid], Q);
    }
}

// ---------------- fused edge kernel (R10-proven) ----------------
#define EDGE_SMEM (34816 + 17408 + 512)
#define EDGE_GRID 512
__global__ void edge_kernel(const int* __restrict__ eidx,
                            const __half* __restrict__ Whg,
                            const float* __restrict__ bm2l) {
    extern __shared__ __align__(16) char smbuf[];
    __half* Wh = (__half*)smbuf;                       // 128 x 136
    __half* Mh = (__half*)(smbuf + 34816);             // 64 x 136
    int*    st = (int*)(smbuf + 34816 + 17408);
    int*    se = st + 64;

    int tid = threadIdx.x;

    for (int i = tid; i < 128*16; i += 256) {
        int r = i >> 4;
        int c8 = (i & 15) << 3;
        uint4 v = *(const uint4*)&Whg[r*128 + c8];
        *(uint4*)&Wh[r*136 + c8] = v;
    }

    int w = tid >> 5;
    int lane = tid & 31;
    int wm = (w & 3) * 16;
    int wn = (w >> 2) * 64;
    int grp = lane >> 2;
    int qt  = lane & 3;
    int lr = lane & 7;
    int lm = lane >> 3;

    u32 a_base = smem_u32(Mh) + (u32)(((wm + (lm & 1)*8 + lr)*136 + (lm >> 1)*8) * 2);
    u32 b_base = smem_u32(Wh) + (u32)((((lm & 1)*8 + lr)*136 + wn + (lm >> 1)*8) * 2);

    for (int tile = blockIdx.x; tile < EE/64; tile += EDGE_GRID) {
        int e0 = tile * 64;
        __syncthreads();
        if (tid < 64) {
            se[tid] = eidx[e0 + tid];
            st[tid] = eidx[EE + e0 + tid];
        }
        __syncthreads();

        for (int i = tid; i < 64*16; i += 256) {
            int e = i >> 4;
            int c8 = (i & 15) << 3;
            uint4 pv = *(const uint4*)&g_Ph[st[e]*128 + c8];
            uint4 qv = *(const uint4*)&g_Qh[se[e]*128 + c8];
            __half2* ph = (__half2*)&pv;
            __half2* qh = (__half2*)&qv;
            uint4 ov;
            __half2* oh = (__half2*)&ov;
            #pragma unroll
            for (int k2 = 0; k2 < 4; k2++) {
                float2 p2 = __half22float2(ph[k2]);
                float2 q2 = __half22float2(qh[k2]);
                oh[k2] = __floats2half2_rn(swishf(p2.x + q2.x), swishf(p2.y + q2.y));
            }
            *(uint4*)&Mh[e*136 + c8] = ov;
        }
        __syncthreads();

        float acc[8][4];
        #pragma unroll
        for (int j = 0; j < 8; j++) {
            #pragma unroll
            for (int i = 0; i < 4; i++) acc[j][i] = 0.f;
        }

        #pragma unroll
        for (int kk = 0; kk < 8; kk++) {
            u32 a0, a1, a2, a3;
            ldsm4(a0, a1, a2, a3, a_base + (u32)(kk*32));
            #pragma unroll
            for (int j = 0; j < 4; j++) {
                u32 b0, b1, b2, b3;
                ldsm4t(b0, b1, b2, b3, b_base + (u32)(kk*4352 + j*32));
                mma16816(acc[2*j],     a0, a1, a2, a3, b0, b1);
                mma16816(acc[2*j + 1], a0, a1, a2, a3, b2, b3);
            }
        }

        int er0 = wm + grp;
        int er1 = er0 + 8;
        int t0 = st[er0];
        int t1 = st[er1];
        #pragma unroll
        for (int j = 0; j < 8; j++) {
            int col = wn + j*8 + 2*qt;
            float b0v = __ldg(&bm2l[col]);
            float b1v = __ldg(&bm2l[col + 1]);
            atomicAdd(&g_agg[t0*128 + col],     swishf(acc[j][0] + b0v));
            atomicAdd(&g_agg[t0*128 + col + 1], swishf(acc[j][1] + b1v));
            atomicAdd(&g_agg[t1*128 + col],     swishf(acc[j][2] + b0v));
            atomicAdd(&g_agg[t1*128 + col + 1], swishf(acc[j][3] + b1v));
        }
    }
}

// ---------------- conv decoder (normalizes h on read) ----------------
__global__ void decoder(const float* __restrict__ u,
                        const float* __restrict__ Wc1, const float* __restrict__ bc1,
                        const float* __restrict__ Wc2, const float* __restrict__ bc2,
                        float* __restrict__ out) {
    __shared__ float hr[128];
    __shared__ float c1[8*38];
    int n = blockIdx.x;
    int bseg = n >> 12;
    int tid = threadIdx.x;
    for (int i = tid; i < 128; i += 64) {
        float v = g_h[n*128 + i];
        hr[i] = (v - __ldg(&g_mean[bseg*128 + i])) * __ldg(&g_rstd[bseg*128 + i]);
    }
    __syncthreads();
    for (int i = tid; i < 8*38; i += 64) {
        int ch = i / 38;
        int p = i % 38;
        float a = __ldg(&bc1[ch]);
        #pragma unroll
        for (int k = 0; k < 16; k++) a += hr[3*p + k] * __ldg(&Wc1[ch*16 + k]);
        c1[i] = swishf(a);
    }
    __syncthreads();
    if (tid < 25) {
        float a = __ldg(&bc2[0]);
        #pragma unroll
        for (int c = 0; c < 8; c++) {
            #pragma unroll
            for (int k = 0; k < 14; k++)
                a += c1[c*38 + tid + k] * __ldg(&Wc2[c*14 + k]);
        }
        float dt = 4.0f / 250.0f;
        out[n*25 + tid] = u[n*25 + 24] + (float)(tid + 1) * dt * a;
    }
}

// ---------------- host ----------------
extern "C" void kernel_launch(void* const* d_in, const int* in_sizes, int n_in,
                              void* d_out, int out_size) {
    const float* u     = (const float*)d_in[0];
    const float* pos   = (const float*)d_in[1];
    const int*   eidx  = (const int*)d_in[2];
    const int*   batch = (const int*)d_in[3];
    const float* We1 = (const float*)d_in[4];
    const float* be1 = (const float*)d_in[5];
    const float* We2 = (const float*)d_in[6];
    const float* be2 = (const float*)d_in[7];
    const float* Wm1 = (const float*)d_in[8];
    const float* bm1 = (const float*)d_in[9];
    const float* Wm2 = (const float*)d_in[10];
    const float* bm2 = (const float*)d_in[11];
    const float* Wu1 = (const float*)d_in[12];
    const float* bu1 = (const float*)d_in[13];
    const float* Wu2 = (const float*)d_in[14];
    const float* bu2 = (const float*)d_in[15];
    const float* Wc1 = (const float*)d_in[16];
    const float* bc1 = (const float*)d_in[17];
    const float* Wc2 = (const float*)d_in[18];
    const float* bc2 = (const float*)d_in[19];
    float* out = (float*)d_out;

    void *a_h = 0, *a_t1 = 0, *a_wm2h = 0, *a_wph = 0, *a_wqh = 0, *a_wu1h = 0, *a_wu2h = 0;
    cudaGetSymbolAddress(&a_h,    g_h);
    cudaGetSymbolAddress(&a_t1,   g_t1);
    cudaGetSymbolAddress(&a_wm2h, g_Wm2h);
    cudaGetSymbolAddress(&a_wph,  g_WPh);
    cudaGetSymbolAddress(&a_wqh,  g_WQh);
    cudaGetSymbolAddress(&a_wu1h, g_Wu1h);
    cudaGetSymbolAddress(&a_wu2h, g_Wu2h);
    float*  h    = (float*)a_h;
    float*  t1   = (float*)a_t1;
    __half* Wm2h = (__half*)a_wm2h;
    __half* WPh  = (__half*)a_wph;
    __half* WQh  = (__half*)a_wqh;
    __half* Wu1h = (__half*)a_wu1h;
    __half* Wu2h = (__half*)a_wu2h;

    int MLP_SMEM_128 = (128*136 + 64*136) * 2;
    cudaFuncSetAttribute(mlp16, cudaFuncAttributeMaxDynamicSharedMemorySize, MLP_SMEM_128);
    cudaFuncSetAttribute(pq_kernel, cudaFuncAttributeMaxDynamicSharedMemorySize, PQ_SMEM);
    cudaFuncSetAttribute(update_kernel, cudaFuncAttributeMaxDynamicSharedMemorySize, UPD_SMEM);
    cudaFuncSetAttribute(edge_kernel, cudaFuncAttributeMaxDynamicSharedMemorySize, EDGE_SMEM);

    convert_wm2<<<(LL*HH*HH/2)/256, 256>>>(Wm2);
    build_pq_w<<<(LL*160*128 + 255)/256, 256>>>(Wm1, bm1);
    build_u_w<<<(LL*256*128 + 255)/256, 256>>>(Wu1, Wu2);
    zero_prep<<<NN/256, 256>>>();
    init_stats<<<(BB*HH + 255)/256, 256>>>();
    prep_node<<<NN/256, 256>>>(pos, batch);
    prep_edge<<<EE/256, 256>>>(eidx);
    fin_cnt<<<NN/256, 256>>>();

    encoder1<<<NN, 128>>>(u, We1, be1);
    mlp16<<<NN/64, 256, MLP_SMEM_128>>>(t1, We2, be2, h);

    for (int l = 0; l < LL; l++) {
        pq_kernel<<<NN/64, 256, PQ_SMEM>>>(WPh + (size_t)l*160*128, WQh + (size_t)l*160*128, u);

        zero_agg<<<(NN*HH/4)/256, 256>>>();
        edge_kernel<<<EDGE_GRID, 256, EDGE_SMEM>>>(eidx, Wm2h + (size_t)l*HH*HH, bm2 + l*128);

        update_kernel<<<NN/64, 256, UPD_SMEM>>>(Wu1h + (size_t)l*256*128,
                                                Wu1 + (size_t)l*257*128 + 256*128,
                                                bu1 + l*128,
                                                Wu2h + (size_t)l*128*128,
                                                bu2 + l*128);

        fin_stats<<<(BB*HH + 255)/256, 256>>>();
    }

    decoder<<<NN, 64>>>(u, Wc1, bc1, Wc2, bc2, out);
}

// round 15
// speedup vs baseline: 1.3504x; 1.0028x over previous
#include <cuda_runtime.h>
#include <cuda_fp16.h>
#include <cstdint>
#include <math.h>

typedef unsigned int u32;

#define NN 32768
#define EE 262144
#define BB 8
#define HH 128
#define LL 6

// ---------------- scratch (device globals; no allocation) ----------------
__device__ __align__(16) float g_h[NN*HH];
__device__ __align__(16) float g_t1[NN*HH];
__device__ __align__(16) __half g_Ph[NN*HH];
__device__ __align__(16) __half g_Qh[NN*HH];
__device__ __align__(16) float g_agg[NN*HH];
__device__ __align__(16) __half g_Wm2h[LL*HH*HH];
__device__ __align__(16) __half g_WPh[LL*160*128];
__device__ __align__(16) __half g_WQh[LL*160*128];
__device__ __align__(16) __half g_Wu1h[LL*256*128];
__device__ __align__(16) __half g_Wu2h[LL*128*128];
__device__ float g_px[NN];
__device__ float g_pt[NN];
__device__ int   g_icnt[NN];
__device__ float g_inv[NN];
__device__ __align__(16) float g_meanb[BB*HH];
__device__ __align__(16) float g_sqb[BB*HH];
__device__ __align__(16) float g_mean[BB*HH];
__device__ __align__(16) float g_rstd[BB*HH];
__device__ float g_gcnt[BB];
__device__ int   g_ctr;

__device__ __forceinline__ float swishf(float x) {
    return x / (1.f + __expf(-x));
}

__device__ __forceinline__ u32 smem_u32(const void* p) {
    return (u32)__cvta_generic_to_shared(p);
}

__device__ __forceinline__ void ldsm4(u32& r0, u32& r1, u32& r2, u32& r3, u32 a) {
    asm volatile("ldmatrix.sync.aligned.m8n8.x4.shared.b16 {%0,%1,%2,%3}, [%4];"
                 : "=r"(r0), "=r"(r1), "=r"(r2), "=r"(r3) : "r"(a));
}

__device__ __forceinline__ void ldsm4t(u32& r0, u32& r1, u32& r2, u32& r3, u32 a) {
    asm volatile("ldmatrix.sync.aligned.m8n8.x4.trans.shared.b16 {%0,%1,%2,%3}, [%4];"
                 : "=r"(r0), "=r"(r1), "=r"(r2), "=r"(r3) : "r"(a));
}

__device__ __forceinline__ void mma16816(float* c, u32 a0, u32 a1, u32 a2, u32 a3,
                                         u32 b0, u32 b1) {
    asm volatile("mma.sync.aligned.m16n8k16.row.col.f32.f16.f16.f32 "
                 "{%0,%1,%2,%3}, {%4,%5,%6,%7}, {%8,%9}, {%0,%1,%2,%3};"
                 : "+f"(c[0]), "+f"(c[1]), "+f"(c[2]), "+f"(c[3])
                 : "r"(a0), "r"(a1), "r"(a2), "r"(a3), "r"(b0), "r"(b1));
}

// ---------------- zero / prep ----------------
__global__ void zero_prep() {
    int i = blockIdx.x * 256 + threadIdx.x;
    if (i < NN) g_icnt[i] = 0;
    if (i < BB) g_gcnt[i] = 0.f;
    if (i == 0) g_ctr = 0;
}

__global__ void init_stats() {
    int i = threadIdx.x + blockIdx.x * 256;
    if (i < BB*HH) {
        g_mean[i] = 0.f;
        g_rstd[i] = 1.f;
        g_meanb[i] = 0.f;
        g_sqb[i]  = 0.f;
    }
}

__global__ void prep_node(const float* __restrict__ pos, const int* __restrict__ batch) {
    int i = blockIdx.x * 256 + threadIdx.x;
    if (i < NN) {
        g_pt[i] = pos[2*i]   * 0.25f;
        g_px[i] = pos[2*i+1] * 0.0625f;
        atomicAdd(&g_gcnt[batch[i]], 1.f);
    }
}

__global__ void prep_edge(const int* __restrict__ eidx) {
    int e = blockIdx.x * 256 + threadIdx.x;
    if (e < EE) atomicAdd(&g_icnt[eidx[EE + e]], 1);
}

__global__ void fin_cnt() {
    int i = blockIdx.x * 256 + threadIdx.x;
    if (i < NN) g_inv[i] = 1.f / (float)max(g_icnt[i], 1);
}

__global__ void convert_wm2(const float* __restrict__ Wm2) {
    int i = blockIdx.x * 256 + threadIdx.x;   // over LL*HH*HH/2
    float2 v = ((const float2*)Wm2)[i];
    ((__half2*)g_Wm2h)[i] = __floats2half2_rn(v.x, v.y);
}

// build folded P/Q weights
__global__ void build_pq_w(const float* __restrict__ Wm1, const float* __restrict__ bm1) {
    int i = blockIdx.x * 256 + threadIdx.x;   // over LL*160*128
    if (i >= LL*160*128) return;
    int l = i / (160*128);
    int r = (i / 128) % 160;
    int c = i & 127;
    const float* W = Wm1 + (size_t)l * 283 * 128;
    float p, q;
    if (r < 128)       { p = W[r*128 + c];              q = W[(128 + r)*128 + c]; }
    else if (r < 153)  { float v = W[(256 + r - 128)*128 + c]; p = v; q = -v; }
    else if (r == 153) { float v = W[281*128 + c];      p = v; q = -v; }
    else if (r == 154) { p = W[282*128 + c];            q = 0.f; }
    else if (r == 155) { p = bm1[l*128 + c];            q = 0.f; }
    else               { p = 0.f;                        q = 0.f; }
    g_WPh[i] = __float2half(p);
    g_WQh[i] = __float2half(q);
}

__global__ void build_u_w(const float* __restrict__ Wu1, const float* __restrict__ Wu2) {
    int i = blockIdx.x * 256 + threadIdx.x;   // over LL*256*128
    if (i >= LL*256*128) return;
    int l = i / (256*128);
    int rc = i % (256*128);
    g_Wu1h[i] = __float2half(Wu1[(size_t)l*257*128 + rc]);
    if (rc < 128*128) g_Wu2h[(size_t)l*128*128 + rc] = __float2half(Wu2[(size_t)l*128*128 + rc]);
}

// ---------------- encoder ----------------
__global__ void encoder1(const float* __restrict__ u, const float* __restrict__ We1,
                         const float* __restrict__ be1) {
    __shared__ float s[27];
    int n = blockIdx.x;
    int t = threadIdx.x;
    if (t < 25)       s[t]  = u[n*25 + t];
    else if (t == 25) s[25] = g_px[n];
    else if (t == 26) s[26] = g_pt[n];
    __syncthreads();
    float a = __ldg(&be1[t]);
    #pragma unroll
    for (int k = 0; k < 27; k++) a += s[k] * __ldg(&We1[k*128 + t]);
    g_t1[n*128 + t] = swishf(a);
}

// generic fp16 GEMM (encoder second layer): out = swish(A@W + b)
__global__ void mlp16(const float* __restrict__ A,
                      const float* __restrict__ W, const float* __restrict__ bias,
                      float* __restrict__ out) {
    extern __shared__ __align__(16) char smbuf[];
    __half* Wh = (__half*)smbuf;            // 128 x 136
    __half* Ah = Wh + 128*136;              // 64 x 136
    const int PA = 136;

    int tid = threadIdx.x;
    int r0g = blockIdx.x * 64;

    for (int i = tid; i < 128*32; i += 256) {
        int k = i >> 5;
        int c4 = (i & 31) << 2;
        float4 v = *(const float4*)&W[k*128 + c4];
        __half2* dst = (__half2*)&Wh[k*136 + c4];
        dst[0] = __floats2half2_rn(v.x, v.y);
        dst[1] = __floats2half2_rn(v.z, v.w);
    }
    for (int i = tid; i < 64*32; i += 256) {
        int r  = i >> 5;
        int k4 = (i & 31) << 2;
        float4 v = *(const float4*)&A[(r0g + r)*128 + k4];
        __half2* dst = (__half2*)&Ah[r*PA + k4];
        dst[0] = __floats2half2_rn(v.x, v.y);
        dst[1] = __floats2half2_rn(v.z, v.w);
    }
    __syncthreads();

    int w = tid >> 5;
    int lane = tid & 31;
    int wm = (w & 3) * 16;
    int wn = (w >> 2) * 64;
    int grp = lane >> 2;
    int qt  = lane & 3;
    int lr = lane & 7;
    int lm = lane >> 3;

    float acc[8][4];
    #pragma unroll
    for (int j = 0; j < 8; j++) {
        #pragma unroll
        for (int i = 0; i < 4; i++) acc[j][i] = 0.f;
    }

    u32 a_base = smem_u32(Ah) + (u32)(((wm + (lm & 1)*8 + lr)*PA + (lm >> 1)*8) * 2);
    u32 b_base = smem_u32(Wh) + (u32)((((lm & 1)*8 + lr)*136 + wn + (lm >> 1)*8) * 2);

    #pragma unroll
    for (int kk = 0; kk < 8; kk++) {
        u32 a0, a1, a2, a3;
        ldsm4(a0, a1, a2, a3, a_base + (u32)(kk*32));
        #pragma unroll
        for (int j = 0; j < 4; j++) {
            u32 b0, b1, b2, b3;
            ldsm4t(b0, b1, b2, b3, b_base + (u32)(kk*4352 + j*32));
            mma16816(acc[2*j],     a0, a1, a2, a3, b0, b1);
            mma16816(acc[2*j + 1], a0, a1, a2, a3, b2, b3);
        }
    }

    #pragma unroll
    for (int j = 0; j < 8; j++) {
        int col = wn + j*8 + 2*qt;
        int r0 = r0g + wm + grp;
        int r1 = r0 + 8;
        float o0 = swishf(acc[j][0] + __ldg(&bias[col]));
        float o1 = swishf(acc[j][1] + __ldg(&bias[col+1]));
        float o2 = swishf(acc[j][2] + __ldg(&bias[col]));
        float o3 = swishf(acc[j][3] + __ldg(&bias[col+1]));
        *(float2*)&out[r0*128 + col] = make_float2(o0, o1);
        *(float2*)&out[r1*128 + col] = make_float2(o2, o3);
    }
}

// ---------------- fused P/Q kernel (K=160, shared A, two GEMMs; also zeroes agg rows) ----------------
#define PQ_SMEM (43520 + 43520 + 21504)
__global__ void __launch_bounds__(256, 2)
pq_kernel(const __half* __restrict__ WPg, const __half* __restrict__ WQg,
          const float* __restrict__ u) {
    extern __shared__ __align__(16) char smbuf[];
    __half* WPs = (__half*)smbuf;                     // 160 x 136
    __half* WQs = (__half*)(smbuf + 43520);           // 160 x 136
    __half* Ah  = (__half*)(smbuf + 87040);           // 64 x 168
    const int PA = 168;

    int tid = threadIdx.x;
    int r0g = blockIdx.x * 64;
    int bseg = r0g >> 12;

    // zero this block's agg rows (edge_kernel runs strictly after in stream order)
    {
        float4 z = make_float4(0.f, 0.f, 0.f, 0.f);
        float4* aggp = (float4*)&g_agg[r0g*128];
        #pragma unroll
        for (int i = tid; i < 64*32; i += 256) aggp[i] = z;
    }

    for (int i = tid; i < 160*16; i += 256) {
        int r = i >> 4;
        int c8 = (i & 15) << 3;
        *(uint4*)&WPs[r*136 + c8] = *(const uint4*)&WPg[r*128 + c8];
        *(uint4*)&WQs[r*136 + c8] = *(const uint4*)&WQg[r*128 + c8];
    }
    for (int i = tid; i < 64*32; i += 256) {
        int r  = i >> 5;
        int k4 = (i & 31) << 2;
        float4 v = *(const float4*)&g_h[(r0g + r)*128 + k4];
        float4 m = *(const float4*)&g_mean[bseg*128 + k4];
        float4 rs = *(const float4*)&g_rstd[bseg*128 + k4];
        v.x = (v.x - m.x)*rs.x;
        v.y = (v.y - m.y)*rs.y;
        v.z = (v.z - m.z)*rs.z;
        v.w = (v.w - m.w)*rs.w;
        __half2* dst = (__half2*)&Ah[r*PA + k4];
        dst[0] = __floats2half2_rn(v.x, v.y);
        dst[1] = __floats2half2_rn(v.z, v.w);
    }
    for (int i = tid; i < 64*32; i += 256) {
        int r = i >> 5;
        int c = 128 + (i & 31);
        int row = r0g + r;
        float v;
        if (c < 153)       v = u[row*25 + (c - 128)];
        else if (c == 153) v = g_px[row];
        else if (c == 154) v = g_pt[row];
        else if (c == 155) v = 1.f;
        else               v = 0.f;
        Ah[r*PA + c] = __float2half(v);
    }
    __syncthreads();

    int w = tid >> 5;
    int lane = tid & 31;
    int wm = (w & 3) * 16;
    int wn = (w >> 2) * 64;
    int grp = lane >> 2;
    int qt  = lane & 3;
    int lr = lane & 7;
    int lm = lane >> 3;

    float accP[8][4], accQ[8][4];
    #pragma unroll
    for (int j = 0; j < 8; j++) {
        #pragma unroll
        for (int i = 0; i < 4; i++) { accP[j][i] = 0.f; accQ[j][i] = 0.f; }
    }

    u32 a_base  = smem_u32(Ah)  + (u32)(((wm + (lm & 1)*8 + lr)*PA + (lm >> 1)*8) * 2);
    u32 bP_base = smem_u32(WPs) + (u32)((((lm & 1)*8 + lr)*136 + wn + (lm >> 1)*8) * 2);
    u32 bQ_base = smem_u32(WQs) + (u32)((((lm & 1)*8 + lr)*136 + wn + (lm >> 1)*8) * 2);

    #pragma unroll
    for (int kk = 0; kk < 10; kk++) {
        u32 a0, a1, a2, a3;
        ldsm4(a0, a1, a2, a3, a_base + (u32)(kk*32));
        #pragma unroll
        for (int j = 0; j < 4; j++) {
            u32 b0, b1, b2, b3;
            ldsm4t(b0, b1, b2, b3, bP_base + (u32)(kk*4352 + j*32));
            mma16816(accP[2*j],     a0, a1, a2, a3, b0, b1);
            mma16816(accP[2*j + 1], a0, a1, a2, a3, b2, b3);
        }
        #pragma unroll
        for (int j = 0; j < 4; j++) {
            u32 b0, b1, b2, b3;
            ldsm4t(b0, b1, b2, b3, bQ_base + (u32)(kk*4352 + j*32));
            mma16816(accQ[2*j],     a0, a1, a2, a3, b0, b1);
            mma16816(accQ[2*j + 1], a0, a1, a2, a3, b2, b3);
        }
    }

    #pragma unroll
    for (int j = 0; j < 8; j++) {
        int col = wn + j*8 + 2*qt;
        int r0 = r0g + wm + grp;
        int r1 = r0 + 8;
        *(__half2*)&g_Ph[r0*128 + col] = __floats2half2_rn(accP[j][0], accP[j][1]);
        *(__half2*)&g_Ph[r1*128 + col] = __floats2half2_rn(accP[j][2], accP[j][3]);
        *(__half2*)&g_Qh[r0*128 + col] = __floats2half2_rn(accQ[j][0], accQ[j][1]);
        *(__half2*)&g_Qh[r1*128 + col] = __floats2half2_rn(accQ[j][2], accQ[j][3]);
    }
}

// ---------------- fused update kernel (two chained GEMMs + norm-stat reduction + last-block finalize) ----------------
#define UPD_SMEM 103424
#define UPD_GRID (NN/64)
__global__ void __launch_bounds__(256, 2)
update_kernel(const __half* __restrict__ Wu1h, const float* __restrict__ wx,
              const float* __restrict__ bu1,
              const __half* __restrict__ Wu2h, const float* __restrict__ bu2) {
    extern __shared__ __align__(16) char smbuf[];
    __half* Wh1 = (__half*)smbuf;                      // 256 x 136 (phase 1)
    __half* Ah  = (__half*)(smbuf + 69632);            // 64 x 264  (phase 1)
    __half* Wh2 = (__half*)smbuf;                      // 128 x 136 (phase 2)
    __half* Hh  = (__half*)(smbuf + 34816);            // 64 x 136  (phase 2)
    float*  Hs  = (float*)(smbuf + 52224);             // 64 x 128  (phase 2)
    float*  ps  = (float*)(smbuf + 84992);             // 256
    float*  qs  = (float*)(smbuf + 86016);             // 256
    __shared__ int islast;
    const int PA = 264;

    int tid = threadIdx.x;
    int r0g = blockIdx.x * 64;
    int bseg = r0g >> 12;

    for (int i = tid; i < 256*16; i += 256) {
        int r = i >> 4;
        int c8 = (i & 15) << 3;
        *(uint4*)&Wh1[r*136 + c8] = *(const uint4*)&Wu1h[r*128 + c8];
    }
    for (int i = tid; i < 64*64; i += 256) {
        int r  = i >> 6;
        int k4 = (i & 63) << 2;
        int row = r0g + r;
        float4 v;
        if (k4 < 128) {
            v = *(const float4*)&g_h[row*128 + k4];
            float4 m = *(const float4*)&g_mean[bseg*128 + k4];
            float4 rs = *(const float4*)&g_rstd[bseg*128 + k4];
            v.x = (v.x - m.x)*rs.x;
            v.y = (v.y - m.y)*rs.y;
            v.z = (v.z - m.z)*rs.z;
            v.w = (v.w - m.w)*rs.w;
        } else {
            v = *(const float4*)&g_agg[row*128 + (k4 - 128)];
            float s = g_inv[row];
            v.x *= s; v.y *= s; v.z *= s; v.w *= s;
        }
        __half2* dst = (__half2*)&Ah[r*PA + k4];
        dst[0] = __floats2half2_rn(v.x, v.y);
        dst[1] = __floats2half2_rn(v.z, v.w);
    }
    __syncthreads();

    int w = tid >> 5;
    int lane = tid & 31;
    int wm = (w & 3) * 16;
    int wn = (w >> 2) * 64;
    int grp = lane >> 2;
    int qt  = lane & 3;
    int lr = lane & 7;
    int lm = lane >> 3;

    float acc[8][4];
    #pragma unroll
    for (int j = 0; j < 8; j++) {
        #pragma unroll
        for (int i = 0; i < 4; i++) acc[j][i] = 0.f;
    }

    u32 a_base = smem_u32(Ah)  + (u32)(((wm + (lm & 1)*8 + lr)*PA + (lm >> 1)*8) * 2);
    u32 b_base = smem_u32(Wh1) + (u32)((((lm & 1)*8 + lr)*136 + wn + (lm >> 1)*8) * 2);

    #pragma unroll
    for (int kk = 0; kk < 16; kk++) {
        u32 a0, a1, a2, a3;
        ldsm4(a0, a1, a2, a3, a_base + (u32)(kk*32));
        #pragma unroll
        for (int j = 0; j < 4; j++) {
            u32 b0, b1, b2, b3;
            ldsm4t(b0, b1, b2, b3, b_base + (u32)(kk*4352 + j*32));
            mma16816(acc[2*j],     a0, a1, a2, a3, b0, b1);
            mma16816(acc[2*j + 1], a0, a1, a2, a3, b2, b3);
        }
    }
    __syncthreads();

    {
        int er0 = wm + grp;
        int er1 = er0 + 8;
        float pt0 = g_pt[r0g + er0], pt1 = g_pt[r0g + er1];
        #pragma unroll
        for (int j = 0; j < 8; j++) {
            int col = wn + j*8 + 2*qt;
            float o0 = swishf(acc[j][0] + pt0*__ldg(&wx[col])   + __ldg(&bu1[col]));
            float o1 = swishf(acc[j][1] + pt0*__ldg(&wx[col+1]) + __ldg(&bu1[col+1]));
            float o2 = swishf(acc[j][2] + pt1*__ldg(&wx[col])   + __ldg(&bu1[col]));
            float o3 = swishf(acc[j][3] + pt1*__ldg(&wx[col+1]) + __ldg(&bu1[col+1]));
            *(__half2*)&Hh[er0*136 + col] = __floats2half2_rn(o0, o1);
            *(__half2*)&Hh[er1*136 + col] = __floats2half2_rn(o2, o3);
        }
    }
    for (int i = tid; i < 128*16; i += 256) {
        int r = i >> 4;
        int c8 = (i & 15) << 3;
        *(uint4*)&Wh2[r*136 + c8] = *(const uint4*)&Wu2h[r*128 + c8];
    }
    __syncthreads();

    #pragma unroll
    for (int j = 0; j < 8; j++) {
        #pragma unroll
        for (int i = 0; i < 4; i++) acc[j][i] = 0.f;
    }
    u32 a2_base = smem_u32(Hh)  + (u32)(((wm + (lm & 1)*8 + lr)*136 + (lm >> 1)*8) * 2);
    u32 b2_base = smem_u32(Wh2) + (u32)((((lm & 1)*8 + lr)*136 + wn + (lm >> 1)*8) * 2);
    #pragma unroll
    for (int kk = 0; kk < 8; kk++) {
        u32 a0, a1, a2, a3;
        ldsm4(a0, a1, a2, a3, a2_base + (u32)(kk*32));
        #pragma unroll
        for (int j = 0; j < 4; j++) {
            u32 b0, b1, b2, b3;
            ldsm4t(b0, b1, b2, b3, b2_base + (u32)(kk*4352 + j*32));
            mma16816(acc[2*j],     a0, a1, a2, a3, b0, b1);
            mma16816(acc[2*j + 1], a0, a1, a2, a3, b2, b3);
        }
    }

    // epilogue2: h_new = norm(h_old) + swish(acc + bu2); write g_h and Hs
    #pragma unroll
    for (int j = 0; j < 8; j++) {
        int col = wn + j*8 + 2*qt;
        int r0 = r0g + wm + grp;
        int r1 = r0 + 8;
        float m0 = __ldg(&g_mean[bseg*128 + col]);
        float m1 = __ldg(&g_mean[bseg*128 + col + 1]);
        float s0 = __ldg(&g_rstd[bseg*128 + col]);
        float s1 = __ldg(&g_rstd[bseg*128 + col + 1]);
        float2 h0 = *(float2*)&g_h[r0*128 + col];
        float2 h1 = *(float2*)&g_h[r1*128 + col];
        h0.x = (h0.x - m0)*s0 + swishf(acc[j][0] + __ldg(&bu2[col]));
        h0.y = (h0.y - m1)*s1 + swishf(acc[j][1] + __ldg(&bu2[col+1]));
        h1.x = (h1.x - m0)*s0 + swishf(acc[j][2] + __ldg(&bu2[col]));
        h1.y = (h1.y - m1)*s1 + swishf(acc[j][3] + __ldg(&bu2[col+1]));
        *(float2*)&g_h[r0*128 + col] = h0;
        *(float2*)&g_h[r1*128 + col] = h1;
        *(float2*)&Hs[(wm + grp)*128 + col] = h0;
        *(float2*)&Hs[(wm + grp + 8)*128 + col] = h1;
    }
    __syncthreads();

    // block-level norm-stat reduction over 64 rows
    {
        int col = tid & 127;
        int half = tid >> 7;
        float s = 0.f, q = 0.f;
        #pragma unroll 8
        for (int r = half*32; r < half*32 + 32; r++) {
            float v = Hs[r*128 + col];
            s += v;
            q += v*v;
        }
        ps[tid] = s;
        qs[tid] = q;
    }
    __syncthreads();
    if (tid < 128) {
        float S = ps[tid] + ps[tid + 128];
        float Q = qs[tid] + qs[tid + 128];
        atomicAdd(&g_meanb[bseg*128 + tid], S);
        atomicAdd(&g_sqb[bseg*128 + tid], Q);
    }

    // last-block finalizes stats for this layer and resets accumulators
    __syncthreads();
    if (tid == 0) {
        __threadfence();
        int prev = atomicAdd(&g_ctr, 1);
        islast = (prev == UPD_GRID - 1) ? 1 : 0;
    }
    __syncthreads();
    if (islast) {
        #pragma unroll
        for (int k = 0; k < 4; k++) {
            int i = tid + k*256;
            int b = i >> 7;
            float gi = 1.f / g_gcnt[b];
            float m = g_meanb[i] * gi;
            float var = g_sqb[i] * gi - m*m;
            g_mean[i] = m;
            g_rstd[i] = rsqrtf(var + 1e-5f);
            g_meanb[i] = 0.f;
            g_sqb[i]  = 0.f;
        }
        __threadfence();
        __syncthreads();
        if (tid == 0) g_ctr = 0;
    }
}

// ---------------- fused edge kernel (R10-proven) ----------------
#define EDGE_SMEM (34816 + 17408 + 512)
#define EDGE_GRID 512
__global__ void edge_kernel(const int* __restrict__ eidx,
                            const __half* __restrict__ Whg,
                            const float* __restrict__ bm2l) {
    extern __shared__ __align__(16) char smbuf[];
    __half* Wh = (__half*)smbuf;                       // 128 x 136
    __half* Mh = (__half*)(smbuf + 34816);             // 64 x 136
    int*    st = (int*)(smbuf + 34816 + 17408);
    int*    se = st + 64;

    int tid = threadIdx.x;

    for (int i = tid; i < 128*16; i += 256) {
        int r = i >> 4;
        int c8 = (i & 15) << 3;
        uint4 v = *(const uint4*)&Whg[r*128 + c8];
        *(uint4*)&Wh[r*136 + c8] = v;
    }

    int w = tid >> 5;
    int lane = tid & 31;
    int wm = (w & 3) * 16;
    int wn = (w >> 2) * 64;
    int grp = lane >> 2;
    int qt  = lane & 3;
    int lr = lane & 7;
    int lm = lane >> 3;

    u32 a_base = smem_u32(Mh) + (u32)(((wm + (lm & 1)*8 + lr)*136 + (lm >> 1)*8) * 2);
    u32 b_base = smem_u32(Wh) + (u32)((((lm & 1)*8 + lr)*136 + wn + (lm >> 1)*8) * 2);

    for (int tile = blockIdx.x; tile < EE/64; tile += EDGE_GRID) {
        int e0 = tile * 64;
        __syncthreads();
        if (tid < 64) {
            se[tid] = eidx[e0 + tid];
            st[tid] = eidx[EE + e0 + tid];
        }
        __syncthreads();

        for (int i = tid; i < 64*16; i += 256) {
            int e = i >> 4;
            int c8 = (i & 15) << 3;
            uint4 pv = *(const uint4*)&g_Ph[st[e]*128 + c8];
            uint4 qv = *(const uint4*)&g_Qh[se[e]*128 + c8];
            __half2* ph = (__half2*)&pv;
            __half2* qh = (__half2*)&qv;
            uint4 ov;
            __half2* oh = (__half2*)&ov;
            #pragma unroll
            for (int k2 = 0; k2 < 4; k2++) {
                float2 p2 = __half22float2(ph[k2]);
                float2 q2 = __half22float2(qh[k2]);
                oh[k2] = __floats2half2_rn(swishf(p2.x + q2.x), swishf(p2.y + q2.y));
            }
            *(uint4*)&Mh[e*136 + c8] = ov;
        }
        __syncthreads();

        float acc[8][4];
        #pragma unroll
        for (int j = 0; j < 8; j++) {
            #pragma unroll
            for (int i = 0; i < 4; i++) acc[j][i] = 0.f;
        }

        #pragma unroll
        for (int kk = 0; kk < 8; kk++) {
            u32 a0, a1, a2, a3;
            ldsm4(a0, a1, a2, a3, a_base + (u32)(kk*32));
            #pragma unroll
            for (int j = 0; j < 4; j++) {
                u32 b0, b1, b2, b3;
                ldsm4t(b0, b1, b2, b3, b_base + (u32)(kk*4352 + j*32));
                mma16816(acc[2*j],     a0, a1, a2, a3, b0, b1);
                mma16816(acc[2*j + 1], a0, a1, a2, a3, b2, b3);
            }
        }

        int er0 = wm + grp;
        int er1 = er0 + 8;
        int t0 = st[er0];
        int t1 = st[er1];
        #pragma unroll
        for (int j = 0; j < 8; j++) {
            int col = wn + j*8 + 2*qt;
            float b0v = __ldg(&bm2l[col]);
            float b1v = __ldg(&bm2l[col + 1]);
            atomicAdd(&g_agg[t0*128 + col],     swishf(acc[j][0] + b0v));
            atomicAdd(&g_agg[t0*128 + col + 1], swishf(acc[j][1] + b1v));
            atomicAdd(&g_agg[t1*128 + col],     swishf(acc[j][2] + b0v));
            atomicAdd(&g_agg[t1*128 + col + 1], swishf(acc[j][3] + b1v));
        }
    }
}

// ---------------- conv decoder (normalizes h on read) ----------------
__global__ void decoder(const float* __restrict__ u,
                        const float* __restrict__ Wc1, const float* __restrict__ bc1,
                        const float* __restrict__ Wc2, const float* __restrict__ bc2,
                        float* __restrict__ out) {
    __shared__ float hr[128];
    __shared__ float c1[8*38];
    int n = blockIdx.x;
    int bseg = n >> 12;
    int tid = threadIdx.x;
    for (int i = tid; i < 128; i += 64) {
        float v = g_h[n*128 + i];
        hr[i] = (v - __ldg(&g_mean[bseg*128 + i])) * __ldg(&g_rstd[bseg*128 + i]);
    }
    __syncthreads();
    for (int i = tid; i < 8*38; i += 64) {
        int ch = i / 38;
        int p = i % 38;
        float a = __ldg(&bc1[ch]);
        #pragma unroll
        for (int k = 0; k < 16; k++) a += hr[3*p + k] * __ldg(&Wc1[ch*16 + k]);
        c1[i] = swishf(a);
    }
    __syncthreads();
    if (tid < 25) {
        float a = __ldg(&bc2[0]);
        #pragma unroll
        for (int c = 0; c < 8; c++) {
            #pragma unroll
            for (int k = 0; k < 14; k++)
                a += c1[c*38 + tid + k] * __ldg(&Wc2[c*14 + k]);
        }
        float dt = 4.0f / 250.0f;
        out[n*25 + tid] = u[n*25 + 24] + (float)(tid + 1) * dt * a;
    }
}

// ---------------- host ----------------
extern "C" void kernel_launch(void* const* d_in, const int* in_sizes, int n_in,
                              void* d_out, int out_size) {
    const float* u     = (const float*)d_in[0];
    const float* pos   = (const float*)d_in[1];
    const int*   eidx  = (const int*)d_in[2];
    const int*   batch = (const int*)d_in[3];
    const float* We1 = (const float*)d_in[4];
    const float* be1 = (const float*)d_in[5];
    const float* We2 = (const float*)d_in[6];
    const float* be2 = (const float*)d_in[7];
    const float* Wm1 = (const float*)d_in[8];
    const float* bm1 = (const float*)d_in[9];
    const float* Wm2 = (const float*)d_in[10];
    const float* bm2 = (const float*)d_in[11];
    const float* Wu1 = (const float*)d_in[12];
    const float* bu1 = (const float*)d_in[13];
    const float* Wu2 = (const float*)d_in[14];
    const float* bu2 = (const float*)d_in[15];
    const float* Wc1 = (const float*)d_in[16];
    const float* bc1 = (const float*)d_in[17];
    const float* Wc2 = (const float*)d_in[18];
    const float* bc2 = (const float*)d_in[19];
    float* out = (float*)d_out;

    void *a_h = 0, *a_t1 = 0, *a_wm2h = 0, *a_wph = 0, *a_wqh = 0, *a_wu1h = 0, *a_wu2h = 0;
    cudaGetSymbolAddress(&a_h,    g_h);
    cudaGetSymbolAddress(&a_t1,   g_t1);
    cudaGetSymbolAddress(&a_wm2h, g_Wm2h);
    cudaGetSymbolAddress(&a_wph,  g_WPh);
    cudaGetSymbolAddress(&a_wqh,  g_WQh);
    cudaGetSymbolAddress(&a_wu1h, g_Wu1h);
    cudaGetSymbolAddress(&a_wu2h, g_Wu2h);
    float*  h    = (float*)a_h;
    float*  t1   = (float*)a_t1;
    __half* Wm2h = (__half*)a_wm2h;
    __half* WPh  = (__half*)a_wph;
    __half* WQh  = (__half*)a_wqh;
    __half* Wu1h = (__half*)a_wu1h;
    __half* Wu2h = (__half*)a_wu2h;

    int MLP_SMEM_128 = (128*136 + 64*136) * 2;
    cudaFuncSetAttribute(mlp16, cudaFuncAttributeMaxDynamicSharedMemorySize, MLP_SMEM_128);
    cudaFuncSetAttribute(pq_kernel, cudaFuncAttributeMaxDynamicSharedMemorySize, PQ_SMEM);
    cudaFuncSetAttribute(update_kernel, cudaFuncAttributeMaxDynamicSharedMemorySize, UPD_SMEM);
    cudaFuncSetAttribute(edge_kernel, cudaFuncAttributeMaxDynamicSharedMemorySize, EDGE_SMEM);

    convert_wm2<<<(LL*HH*HH/2)/256, 256>>>(Wm2);
    build_pq_w<<<(LL*160*128 + 255)/256, 256>>>(Wm1, bm1);
    build_u_w<<<(LL*256*128 + 255)/256, 256>>>(Wu1, Wu2);
    zero_prep<<<NN/256, 256>>>();
    init_stats<<<(BB*HH + 255)/256, 256>>>();
    prep_node<<<NN/256, 256>>>(pos, batch);
    prep_edge<<<EE/256, 256>>>(eidx);
    fin_cnt<<<NN/256, 256>>>();

    encoder1<<<NN, 128>>>(u, We1, be1);
    mlp16<<<NN/64, 256, MLP_SMEM_128>>>(t1, We2, be2, h);

    for (int l = 0; l < LL; l++) {
        pq_kernel<<<NN/64, 256, PQ_SMEM>>>(WPh + (size_t)l*160*128, WQh + (size_t)l*160*128, u);

        edge_kernel<<<EDGE_GRID, 256, EDGE_SMEM>>>(eidx, Wm2h + (size_t)l*HH*HH, bm2 + l*128);

        update_kernel<<<UPD_GRID, 256, UPD_SMEM>>>(Wu1h + (size_t)l*256*128,
                                                   Wu1 + (size_t)l*257*128 + 256*128,
                                                   bu1 + l*128,
                                                   Wu2h + (size_t)l*128*128,
                                                   bu2 + l*128);
    }

    decoder<<<NN, 64>>>(u, Wc1, bc1, Wc2, bc2, out);
}

// round 17
// speedup vs baseline: 1.4091x; 1.0435x over previous
#include <cuda_runtime.h>
#include <cuda_fp16.h>
#include <cstdint>
#include <math.h>

typedef unsigned int u32;

#define NN 32768
#define EE 262144
#define BB 8
#define HH 128
#define LL 6

// ---------------- scratch (device globals; no allocation) ----------------
__device__ __align__(16) float g_h[NN*HH];
__device__ __align__(16) float g_t1[NN*HH];
__device__ __align__(16) __half g_Ph[NN*HH];
__device__ __align__(16) __half g_Qh[NN*HH];
__device__ __align__(16) float g_agg[NN*HH];
__device__ __align__(16) __half g_Wm2h[LL*HH*HH];
__device__ __align__(16) __half g_WPh[LL*160*128];
__device__ __align__(16) __half g_WQh[LL*160*128];
__device__ __align__(16) __half g_Wu1h[LL*256*128];
__device__ __align__(16) __half g_Wu2h[LL*128*128];
__device__ float g_px[NN];
__device__ float g_pt[NN];
__device__ int   g_icnt[NN];
__device__ float g_inv[NN];
__device__ __align__(16) float g_meanb[BB*HH];
__device__ __align__(16) float g_sqb[BB*HH];
__device__ __align__(16) float g_mean[BB*HH];
__device__ __align__(16) float g_rstd[BB*HH];
__device__ float g_gcnt[BB];
__device__ int   g_ctr;

__device__ __forceinline__ float swishf(float x) {
    return x / (1.f + __expf(-x));
}

__device__ __forceinline__ u32 smem_u32(const void* p) {
    return (u32)__cvta_generic_to_shared(p);
}

__device__ __forceinline__ void ldsm4(u32& r0, u32& r1, u32& r2, u32& r3, u32 a) {
    asm volatile("ldmatrix.sync.aligned.m8n8.x4.shared.b16 {%0,%1,%2,%3}, [%4];"
                 : "=r"(r0), "=r"(r1), "=r"(r2), "=r"(r3) : "r"(a));
}

__device__ __forceinline__ void ldsm4t(u32& r0, u32& r1, u32& r2, u32& r3, u32 a) {
    asm volatile("ldmatrix.sync.aligned.m8n8.x4.trans.shared.b16 {%0,%1,%2,%3}, [%4];"
                 : "=r"(r0), "=r"(r1), "=r"(r2), "=r"(r3) : "r"(a));
}

__device__ __forceinline__ void mma16816(float* c, u32 a0, u32 a1, u32 a2, u32 a3,
                                         u32 b0, u32 b1) {
    asm volatile("mma.sync.aligned.m16n8k16.row.col.f32.f16.f16.f32 "
                 "{%0,%1,%2,%3}, {%4,%5,%6,%7}, {%8,%9}, {%0,%1,%2,%3};"
                 : "+f"(c[0]), "+f"(c[1]), "+f"(c[2]), "+f"(c[3])
                 : "r"(a0), "r"(a1), "r"(a2), "r"(a3), "r"(b0), "r"(b1));
}

// vectorized fp32 reduction: one RED lane carries 16 bytes
__device__ __forceinline__ void red_v4(float* p, float4 v) {
    asm volatile("red.global.add.v4.f32 [%0], {%1,%2,%3,%4};"
                 :: "l"(p), "f"(v.x), "f"(v.y), "f"(v.z), "f"(v.w) : "memory");
}

// ---------------- zero / prep ----------------
__global__ void zero_prep() {
    int i = blockIdx.x * 256 + threadIdx.x;
    if (i < NN) g_icnt[i] = 0;
    if (i < BB) g_gcnt[i] = 0.f;
    if (i == 0) g_ctr = 0;
}

__global__ void init_stats() {
    int i = threadIdx.x + blockIdx.x * 256;
    if (i < BB*HH) {
        g_mean[i] = 0.f;
        g_rstd[i] = 1.f;
        g_meanb[i] = 0.f;
        g_sqb[i]  = 0.f;
    }
}

__global__ void prep_node(const float* __restrict__ pos, const int* __restrict__ batch) {
    int i = blockIdx.x * 256 + threadIdx.x;
    if (i < NN) {
        g_pt[i] = pos[2*i]   * 0.25f;
        g_px[i] = pos[2*i+1] * 0.0625f;
        atomicAdd(&g_gcnt[batch[i]], 1.f);
    }
}

__global__ void prep_edge(const int* __restrict__ eidx) {
    int e = blockIdx.x * 256 + threadIdx.x;
    if (e < EE) atomicAdd(&g_icnt[eidx[EE + e]], 1);
}

__global__ void fin_cnt() {
    int i = blockIdx.x * 256 + threadIdx.x;
    if (i < NN) g_inv[i] = 1.f / (float)max(g_icnt[i], 1);
}

__global__ void convert_wm2(const float* __restrict__ Wm2) {
    int i = blockIdx.x * 256 + threadIdx.x;   // over LL*HH*HH/2
    float2 v = ((const float2*)Wm2)[i];
    ((__half2*)g_Wm2h)[i] = __floats2half2_rn(v.x, v.y);
}

// build folded P/Q weights
__global__ void build_pq_w(const float* __restrict__ Wm1, const float* __restrict__ bm1) {
    int i = blockIdx.x * 256 + threadIdx.x;   // over LL*160*128
    if (i >= LL*160*128) return;
    int l = i / (160*128);
    int r = (i / 128) % 160;
    int c = i & 127;
    const float* W = Wm1 + (size_t)l * 283 * 128;
    float p, q;
    if (r < 128)       { p = W[r*128 + c];              q = W[(128 + r)*128 + c]; }
    else if (r < 153)  { float v = W[(256 + r - 128)*128 + c]; p = v; q = -v; }
    else if (r == 153) { float v = W[281*128 + c];      p = v; q = -v; }
    else if (r == 154) { p = W[282*128 + c];            q = 0.f; }
    else if (r == 155) { p = bm1[l*128 + c];            q = 0.f; }
    else               { p = 0.f;                        q = 0.f; }
    g_WPh[i] = __float2half(p);
    g_WQh[i] = __float2half(q);
}

__global__ void build_u_w(const float* __restrict__ Wu1, const float* __restrict__ Wu2) {
    int i = blockIdx.x * 256 + threadIdx.x;   // over LL*256*128
    if (i >= LL*256*128) return;
    int l = i / (256*128);
    int rc = i % (256*128);
    g_Wu1h[i] = __float2half(Wu1[(size_t)l*257*128 + rc]);
    if (rc < 128*128) g_Wu2h[(size_t)l*128*128 + rc] = __float2half(Wu2[(size_t)l*128*128 + rc]);
}

// ---------------- encoder ----------------
__global__ void encoder1(const float* __restrict__ u, const float* __restrict__ We1,
                         const float* __restrict__ be1) {
    __shared__ float s[27];
    int n = blockIdx.x;
    int t = threadIdx.x;
    if (t < 25)       s[t]  = u[n*25 + t];
    else if (t == 25) s[25] = g_px[n];
    else if (t == 26) s[26] = g_pt[n];
    __syncthreads();
    float a = __ldg(&be1[t]);
    #pragma unroll
    for (int k = 0; k < 27; k++) a += s[k] * __ldg(&We1[k*128 + t]);
    g_t1[n*128 + t] = swishf(a);
}

// generic fp16 GEMM (encoder second layer): out = swish(A@W + b)
__global__ void mlp16(const float* __restrict__ A,
                      const float* __restrict__ W, const float* __restrict__ bias,
                      float* __restrict__ out) {
    extern __shared__ __align__(16) char smbuf[];
    __half* Wh = (__half*)smbuf;            // 128 x 136
    __half* Ah = Wh + 128*136;              // 64 x 136
    const int PA = 136;

    int tid = threadIdx.x;
    int r0g = blockIdx.x * 64;

    for (int i = tid; i < 128*32; i += 256) {
        int k = i >> 5;
        int c4 = (i & 31) << 2;
        float4 v = *(const float4*)&W[k*128 + c4];
        __half2* dst = (__half2*)&Wh[k*136 + c4];
        dst[0] = __floats2half2_rn(v.x, v.y);
        dst[1] = __floats2half2_rn(v.z, v.w);
    }
    for (int i = tid; i < 64*32; i += 256) {
        int r  = i >> 5;
        int k4 = (i & 31) << 2;
        float4 v = *(const float4*)&A[(r0g + r)*128 + k4];
        __half2* dst = (__half2*)&Ah[r*PA + k4];
        dst[0] = __floats2half2_rn(v.x, v.y);
        dst[1] = __floats2half2_rn(v.z, v.w);
    }
    __syncthreads();

    int w = tid >> 5;
    int lane = tid & 31;
    int wm = (w & 3) * 16;
    int wn = (w >> 2) * 64;
    int grp = lane >> 2;
    int qt  = lane & 3;
    int lr = lane & 7;
    int lm = lane >> 3;

    float acc[8][4];
    #pragma unroll
    for (int j = 0; j < 8; j++) {
        #pragma unroll
        for (int i = 0; i < 4; i++) acc[j][i] = 0.f;
    }

    u32 a_base = smem_u32(Ah) + (u32)(((wm + (lm & 1)*8 + lr)*PA + (lm >> 1)*8) * 2);
    u32 b_base = smem_u32(Wh) + (u32)((((lm & 1)*8 + lr)*136 + wn + (lm >> 1)*8) * 2);

    #pragma unroll
    for (int kk = 0; kk < 8; kk++) {
        u32 a0, a1, a2, a3;
        ldsm4(a0, a1, a2, a3, a_base + (u32)(kk*32));
        #pragma unroll
        for (int j = 0; j < 4; j++) {
            u32 b0, b1, b2, b3;
            ldsm4t(b0, b1, b2, b3, b_base + (u32)(kk*4352 + j*32));
            mma16816(acc[2*j],     a0, a1, a2, a3, b0, b1);
            mma16816(acc[2*j + 1], a0, a1, a2, a3, b2, b3);
        }
    }

    #pragma unroll
    for (int j = 0; j < 8; j++) {
        int col = wn + j*8 + 2*qt;
        int r0 = r0g + wm + grp;
        int r1 = r0 + 8;
        float o0 = swishf(acc[j][0] + __ldg(&bias[col]));
        float o1 = swishf(acc[j][1] + __ldg(&bias[col+1]));
        float o2 = swishf(acc[j][2] + __ldg(&bias[col]));
        float o3 = swishf(acc[j][3] + __ldg(&bias[col+1]));
        *(float2*)&out[r0*128 + col] = make_float2(o0, o1);
        *(float2*)&out[r1*128 + col] = make_float2(o2, o3);
    }
}

// ---------------- fused P/Q kernel (K=160, shared A, two GEMMs; also zeroes agg rows) ----------------
#define PQ_SMEM (43520 + 43520 + 21504)
__global__ void __launch_bounds__(256, 2)
pq_kernel(const __half* __restrict__ WPg, const __half* __restrict__ WQg,
          const float* __restrict__ u) {
    extern __shared__ __align__(16) char smbuf[];
    __half* WPs = (__half*)smbuf;                     // 160 x 136
    __half* WQs = (__half*)(smbuf + 43520);           // 160 x 136
    __half* Ah  = (__half*)(smbuf + 87040);           // 64 x 168
    const int PA = 168;

    int tid = threadIdx.x;
    int r0g = blockIdx.x * 64;
    int bseg = r0g >> 12;

    // zero this block's agg rows (edge_kernel runs strictly after in stream order)
    {
        float4 z = make_float4(0.f, 0.f, 0.f, 0.f);
        float4* aggp = (float4*)&g_agg[r0g*128];
        #pragma unroll
        for (int i = tid; i < 64*32; i += 256) aggp[i] = z;
    }

    for (int i = tid; i < 160*16; i += 256) {
        int r = i >> 4;
        int c8 = (i & 15) << 3;
        *(uint4*)&WPs[r*136 + c8] = *(const uint4*)&WPg[r*128 + c8];
        *(uint4*)&WQs[r*136 + c8] = *(const uint4*)&WQg[r*128 + c8];
    }
    for (int i = tid; i < 64*32; i += 256) {
        int r  = i >> 5;
        int k4 = (i & 31) << 2;
        float4 v = *(const float4*)&g_h[(r0g + r)*128 + k4];
        float4 m = *(const float4*)&g_mean[bseg*128 + k4];
        float4 rs = *(const float4*)&g_rstd[bseg*128 + k4];
        v.x = (v.x - m.x)*rs.x;
        v.y = (v.y - m.y)*rs.y;
        v.z = (v.z - m.z)*rs.z;
        v.w = (v.w - m.w)*rs.w;
        __half2* dst = (__half2*)&Ah[r*PA + k4];
        dst[0] = __floats2half2_rn(v.x, v.y);
        dst[1] = __floats2half2_rn(v.z, v.w);
    }
    for (int i = tid; i < 64*32; i += 256) {
        int r = i >> 5;
        int c = 128 + (i & 31);
        int row = r0g + r;
        float v;
        if (c < 153)       v = u[row*25 + (c - 128)];
        else if (c == 153) v = g_px[row];
        else if (c == 154) v = g_pt[row];
        else if (c == 155) v = 1.f;
        else               v = 0.f;
        Ah[r*PA + c] = __float2half(v);
    }
    __syncthreads();

    int w = tid >> 5;
    int lane = tid & 31;
    int wm = (w & 3) * 16;
    int wn = (w >> 2) * 64;
    int grp = lane >> 2;
    int qt  = lane & 3;
    int lr = lane & 7;
    int lm = lane >> 3;

    float accP[8][4], accQ[8][4];
    #pragma unroll
    for (int j = 0; j < 8; j++) {
        #pragma unroll
        for (int i = 0; i < 4; i++) { accP[j][i] = 0.f; accQ[j][i] = 0.f; }
    }

    u32 a_base  = smem_u32(Ah)  + (u32)(((wm + (lm & 1)*8 + lr)*PA + (lm >> 1)*8) * 2);
    u32 bP_base = smem_u32(WPs) + (u32)((((lm & 1)*8 + lr)*136 + wn + (lm >> 1)*8) * 2);
    u32 bQ_base = smem_u32(WQs) + (u32)((((lm & 1)*8 + lr)*136 + wn + (lm >> 1)*8) * 2);

    #pragma unroll
    for (int kk = 0; kk < 10; kk++) {
        u32 a0, a1, a2, a3;
        ldsm4(a0, a1, a2, a3, a_base + (u32)(kk*32));
        #pragma unroll
        for (int j = 0; j < 4; j++) {
            u32 b0, b1, b2, b3;
            ldsm4t(b0, b1, b2, b3, bP_base + (u32)(kk*4352 + j*32));
            mma16816(accP[2*j],     a0, a1, a2, a3, b0, b1);
            mma16816(accP[2*j + 1], a0, a1, a2, a3, b2, b3);
        }
        #pragma unroll
        for (int j = 0; j < 4; j++) {
            u32 b0, b1, b2, b3;
            ldsm4t(b0, b1, b2, b3, bQ_base + (u32)(kk*4352 + j*32));
            mma16816(accQ[2*j],     a0, a1, a2, a3, b0, b1);
            mma16816(accQ[2*j + 1], a0, a1, a2, a3, b2, b3);
        }
    }

    #pragma unroll
    for (int j = 0; j < 8; j++) {
        int col = wn + j*8 + 2*qt;
        int r0 = r0g + wm + grp;
        int r1 = r0 + 8;
        *(__half2*)&g_Ph[r0*128 + col] = __floats2half2_rn(accP[j][0], accP[j][1]);
        *(__half2*)&g_Ph[r1*128 + col] = __floats2half2_rn(accP[j][2], accP[j][3]);
        *(__half2*)&g_Qh[r0*128 + col] = __floats2half2_rn(accQ[j][0], accQ[j][1]);
        *(__half2*)&g_Qh[r1*128 + col] = __floats2half2_rn(accQ[j][2], accQ[j][3]);
    }
}

// ---------------- fused update kernel (two chained GEMMs + norm-stat reduction + last-block finalize) ----------------
#define UPD_SMEM 103424
#define UPD_GRID (NN/64)
__global__ void __launch_bounds__(256, 2)
update_kernel(const __half* __restrict__ Wu1h, const float* __restrict__ wx,
              const float* __restrict__ bu1,
              const __half* __restrict__ Wu2h, const float* __restrict__ bu2) {
    extern __shared__ __align__(16) char smbuf[];
    __half* Wh1 = (__half*)smbuf;                      // 256 x 136 (phase 1)
    __half* Ah  = (__half*)(smbuf + 69632);            // 64 x 264  (phase 1)
    __half* Wh2 = (__half*)smbuf;                      // 128 x 136 (phase 2)
    __half* Hh  = (__half*)(smbuf + 34816);            // 64 x 136  (phase 2)
    float*  Hs  = (float*)(smbuf + 52224);             // 64 x 128  (phase 2)
    float*  ps  = (float*)(smbuf + 84992);             // 256
    float*  qs  = (float*)(smbuf + 86016);             // 256
    __shared__ int islast;
    const int PA = 264;

    int tid = threadIdx.x;
    int r0g = blockIdx.x * 64;
    int bseg = r0g >> 12;

    for (int i = tid; i < 256*16; i += 256) {
        int r = i >> 4;
        int c8 = (i & 15) << 3;
        *(uint4*)&Wh1[r*136 + c8] = *(const uint4*)&Wu1h[r*128 + c8];
    }
    for (int i = tid; i < 64*64; i += 256) {
        int r  = i >> 6;
        int k4 = (i & 63) << 2;
        int row = r0g + r;
        float4 v;
        if (k4 < 128) {
            v = *(const float4*)&g_h[row*128 + k4];
            float4 m = *(const float4*)&g_mean[bseg*128 + k4];
            float4 rs = *(const float4*)&g_rstd[bseg*128 + k4];
            v.x = (v.x - m.x)*rs.x;
            v.y = (v.y - m.y)*rs.y;
            v.z = (v.z - m.z)*rs.z;
            v.w = (v.w - m.w)*rs.w;
        } else {
            v = *(const float4*)&g_agg[row*128 + (k4 - 128)];
            float s = g_inv[row];
            v.x *= s; v.y *= s; v.z *= s; v.w *= s;
        }
        __half2* dst = (__half2*)&Ah[r*PA + k4];
        dst[0] = __floats2half2_rn(v.x, v.y);
        dst[1] = __floats2half2_rn(v.z, v.w);
    }
    __syncthreads();

    int w = tid >> 5;
    int lane = tid & 31;
    int wm = (w & 3) * 16;
    int wn = (w >> 2) * 64;
    int grp = lane >> 2;
    int qt  = lane & 3;
    int lr = lane & 7;
    int lm = lane >> 3;

    float acc[8][4];
    #pragma unroll
    for (int j = 0; j < 8; j++) {
        #pragma unroll
        for (int i = 0; i < 4; i++) acc[j][i] = 0.f;
    }

    u32 a_base = smem_u32(Ah)  + (u32)(((wm + (lm & 1)*8 + lr)*PA + (lm >> 1)*8) * 2);
    u32 b_base = smem_u32(Wh1) + (u32)((((lm & 1)*8 + lr)*136 + wn + (lm >> 1)*8) * 2);

    #pragma unroll
    for (int kk = 0; kk < 16; kk++) {
        u32 a0, a1, a2, a3;
        ldsm4(a0, a1, a2, a3, a_base + (u32)(kk*32));
        #pragma unroll
        for (int j = 0; j < 4; j++) {
            u32 b0, b1, b2, b3;
            ldsm4t(b0, b1, b2, b3, b_base + (u32)(kk*4352 + j*32));
            mma16816(acc[2*j],     a0, a1, a2, a3, b0, b1);
            mma16816(acc[2*j + 1], a0, a1, a2, a3, b2, b3);
        }
    }
    __syncthreads();

    {
        int er0 = wm + grp;
        int er1 = er0 + 8;
        float pt0 = g_pt[r0g + er0], pt1 = g_pt[r0g + er1];
        #pragma unroll
        for (int j = 0; j < 8; j++) {
            int col = wn + j*8 + 2*qt;
            float o0 = swishf(acc[j][0] + pt0*__ldg(&wx[col])   + __ldg(&bu1[col]));
            float o1 = swishf(acc[j][1] + pt0*__ldg(&wx[col+1]) + __ldg(&bu1[col+1]));
            float o2 = swishf(acc[j][2] + pt1*__ldg(&wx[col])   + __ldg(&bu1[col]));
            float o3 = swishf(acc[j][3] + pt1*__ldg(&wx[col+1]) + __ldg(&bu1[col+1]));
            *(__half2*)&Hh[er0*136 + col] = __floats2half2_rn(o0, o1);
            *(__half2*)&Hh[er1*136 + col] = __floats2half2_rn(o2, o3);
        }
    }
    for (int i = tid; i < 128*16; i += 256) {
        int r = i >> 4;
        int c8 = (i & 15) << 3;
        *(uint4*)&Wh2[r*136 + c8] = *(const uint4*)&Wu2h[r*128 + c8];
    }
    __syncthreads();

    #pragma unroll
    for (int j = 0; j < 8; j++) {
        #pragma unroll
        for (int i = 0; i < 4; i++) acc[j][i] = 0.f;
    }
    u32 a2_base = smem_u32(Hh)  + (u32)(((wm + (lm & 1)*8 + lr)*136 + (lm >> 1)*8) * 2);
    u32 b2_base = smem_u32(Wh2) + (u32)((((lm & 1)*8 + lr)*136 + wn + (lm >> 1)*8) * 2);
    #pragma unroll
    for (int kk = 0; kk < 8; kk++) {
        u32 a0, a1, a2, a3;
        ldsm4(a0, a1, a2, a3, a2_base + (u32)(kk*32));
        #pragma unroll
        for (int j = 0; j < 4; j++) {
            u32 b0, b1, b2, b3;
            ldsm4t(b0, b1, b2, b3, b2_base + (u32)(kk*4352 + j*32));
            mma16816(acc[2*j],     a0, a1, a2, a3, b0, b1);
            mma16816(acc[2*j + 1], a0, a1, a2, a3, b2, b3);
        }
    }

    // epilogue2: h_new = norm(h_old) + swish(acc + bu2); write g_h and Hs
    #pragma unroll
    for (int j = 0; j < 8; j++) {
        int col = wn + j*8 + 2*qt;
        int r0 = r0g + wm + grp;
        int r1 = r0 + 8;
        float m0 = __ldg(&g_mean[bseg*128 + col]);
        float m1 = __ldg(&g_mean[bseg*128 + col + 1]);
        float s0 = __ldg(&g_rstd[bseg*128 + col]);
        float s1 = __ldg(&g_rstd[bseg*128 + col + 1]);
        float2 h0 = *(float2*)&g_h[r0*128 + col];
        float2 h1 = *(float2*)&g_h[r1*128 + col];
        h0.x = (h0.x - m0)*s0 + swishf(acc[j][0] + __ldg(&bu2[col]));
        h0.y = (h0.y - m1)*s1 + swishf(acc[j][1] + __ldg(&bu2[col+1]));
        h1.x = (h1.x - m0)*s0 + swishf(acc[j][2] + __ldg(&bu2[col]));
        h1.y = (h1.y - m1)*s1 + swishf(acc[j][3] + __ldg(&bu2[col+1]));
        *(float2*)&g_h[r0*128 + col] = h0;
        *(float2*)&g_h[r1*128 + col] = h1;
        *(float2*)&Hs[(wm + grp)*128 + col] = h0;
        *(float2*)&Hs[(wm + grp + 8)*128 + col] = h1;
    }
    __syncthreads();

    // block-level norm-stat reduction over 64 rows
    {
        int col = tid & 127;
        int half = tid >> 7;
        float s = 0.f, q = 0.f;
        #pragma unroll 8
        for (int r = half*32; r < half*32 + 32; r++) {
            float v = Hs[r*128 + col];
            s += v;
            q += v*v;
        }
        ps[tid] = s;
        qs[tid] = q;
    }
    __syncthreads();
    if (tid < 128) {
        float S = ps[tid] + ps[tid + 128];
        float Q = qs[tid] + qs[tid + 128];
        atomicAdd(&g_meanb[bseg*128 + tid], S);
        atomicAdd(&g_sqb[bseg*128 + tid], Q);
    }

    // last-block finalizes stats for this layer and resets accumulators
    __syncthreads();
    if (tid == 0) {
        __threadfence();
        int prev = atomicAdd(&g_ctr, 1);
        islast = (prev == UPD_GRID - 1) ? 1 : 0;
    }
    __syncthreads();
    if (islast) {
        #pragma unroll
        for (int k = 0; k < 4; k++) {
            int i = tid + k*256;
            int b = i >> 7;
            float gi = 1.f / g_gcnt[b];
            float m = g_meanb[i] * gi;
            float var = g_sqb[i] * gi - m*m;
            g_mean[i] = m;
            g_rstd[i] = rsqrtf(var + 1e-5f);
            g_meanb[i] = 0.f;
            g_sqb[i]  = 0.f;
        }
        __threadfence();
        __syncthreads();
        if (tid == 0) g_ctr = 0;
    }
}

// ---------------- fused edge kernel: persistent W, fp16 gathers, v4 packed scatter ----------------
#define EDGE_SMEM (34816 + 17408 + 512)
#define EDGE_GRID 512
__global__ void edge_kernel(const int* __restrict__ eidx,
                            const __half* __restrict__ Whg,
                            const float* __restrict__ bm2l) {
    extern __shared__ __align__(16) char smbuf[];
    __half* Wh = (__half*)smbuf;                       // 128 x 136
    __half* Mh = (__half*)(smbuf + 34816);             // 64 x 136
    int*    st = (int*)(smbuf + 34816 + 17408);
    int*    se = st + 64;

    int tid = threadIdx.x;

    for (int i = tid; i < 128*16; i += 256) {
        int r = i >> 4;
        int c8 = (i & 15) << 3;
        uint4 v = *(const uint4*)&Whg[r*128 + c8];
        *(uint4*)&Wh[r*136 + c8] = v;
    }

    int w = tid >> 5;
    int lane = tid & 31;
    int wm = (w & 3) * 16;
    int wn = (w >> 2) * 64;
    int grp = lane >> 2;
    int qt  = lane & 3;
    int lr = lane & 7;
    int lm = lane >> 3;

    u32 a_base = smem_u32(Mh) + (u32)(((wm + (lm & 1)*8 + lr)*136 + (lm >> 1)*8) * 2);
    u32 b_base = smem_u32(Wh) + (u32)((((lm & 1)*8 + lr)*136 + wn + (lm >> 1)*8) * 2);

    for (int tile = blockIdx.x; tile < EE/64; tile += EDGE_GRID) {
        int e0 = tile * 64;
        __syncthreads();
        if (tid < 64) {
            se[tid] = eidx[e0 + tid];
            st[tid] = eidx[EE + e0 + tid];
        }
        __syncthreads();

        for (int i = tid; i < 64*16; i += 256) {
            int e = i >> 4;
            int c8 = (i & 15) << 3;
            uint4 pv = *(const uint4*)&g_Ph[st[e]*128 + c8];
            uint4 qv = *(const uint4*)&g_Qh[se[e]*128 + c8];
            __half2* ph = (__half2*)&pv;
            __half2* qh = (__half2*)&qv;
            uint4 ov;
            __half2* oh = (__half2*)&ov;
            #pragma unroll
            for (int k2 = 0; k2 < 4; k2++) {
                float2 p2 = __half22float2(ph[k2]);
                float2 q2 = __half22float2(qh[k2]);
                oh[k2] = __floats2half2_rn(swishf(p2.x + q2.x), swishf(p2.y + q2.y));
            }
            *(uint4*)&Mh[e*136 + c8] = ov;
        }
        __syncthreads();

        float acc[8][4];
        #pragma unroll
        for (int j = 0; j < 8; j++) {
            #pragma unroll
            for (int i = 0; i < 4; i++) acc[j][i] = 0.f;
        }

        #pragma unroll
        for (int kk = 0; kk < 8; kk++) {
            u32 a0, a1, a2, a3;
            ldsm4(a0, a1, a2, a3, a_base + (u32)(kk*32));
            #pragma unroll
            for (int j = 0; j < 4; j++) {
                u32 b0, b1, b2, b3;
                ldsm4t(b0, b1, b2, b3, b_base + (u32)(kk*4352 + j*32));
                mma16816(acc[2*j],     a0, a1, a2, a3, b0, b1);
                mma16816(acc[2*j + 1], a0, a1, a2, a3, b2, b3);
            }
        }

        // second swish + v4 packed scatter:
        // lanes (qt, qt^1) exchange pairs so each lane emits ONE red.v4 per j:
        // even qt -> row t0, cols [base..base+3]; odd qt -> row t1, cols [base..base+3]
        int er0 = wm + grp;
        int er1 = er0 + 8;
        int t0 = st[er0];
        int t1 = st[er1];
        int odd = qt & 1;
        int cb4 = (qt >> 1) << 2;     // 0 or 4 within the j*8 group
        int trow = odd ? t1 : t0;
        #pragma unroll
        for (int j = 0; j < 8; j++) {
            int col = wn + j*8 + 2*qt;
            float b0v = __ldg(&bm2l[col]);
            float b1v = __ldg(&bm2l[col + 1]);
            float e0a = swishf(acc[j][0] + b0v);
            float e0b = swishf(acc[j][1] + b1v);
            float e1a = swishf(acc[j][2] + b0v);
            float e1b = swishf(acc[j][3] + b1v);
            // even lane sends its er1 pair (partner needs it); odd sends er0 pair
            float sa = odd ? e0a : e1a;
            float sb = odd ? e0b : e1b;
            float ra = __shfl_xor_sync(0xffffffffu, sa, 1);
            float rb = __shfl_xor_sync(0xffffffffu, sb, 1);
            float4 val = odd ? make_float4(ra, rb, e1a, e1b)
                             : make_float4(e0a, e0b, ra, rb);
            red_v4(&g_agg[trow*128 + wn + j*8 + cb4], val);
        }
    }
}

// ---------------- conv decoder (normalizes h on read) ----------------
__global__ void decoder(const float* __restrict__ u,
                        const float* __restrict__ Wc1, const float* __restrict__ bc1,
                        const float* __restrict__ Wc2, const float* __restrict__ bc2,
                        float* __restrict__ out) {
    __shared__ float hr[128];
    __shared__ float c1[8*38];
    int n = blockIdx.x;
    int bseg = n >> 12;
    int tid = threadIdx.x;
    for (int i = tid; i < 128; i += 64) {
        float v = g_h[n*128 + i];
        hr[i] = (v - __ldg(&g_mean[bseg*128 + i])) * __ldg(&g_rstd[bseg*128 + i]);
    }
    __syncthreads();
    for (int i = tid; i < 8*38; i += 64) {
        int ch = i / 38;
        int p = i % 38;
        float a = __ldg(&bc1[ch]);
        #pragma unroll
        for (int k = 0; k < 16; k++) a += hr[3*p + k] * __ldg(&Wc1[ch*16 + k]);
        c1[i] = swishf(a);
    }
    __syncthreads();
    if (tid < 25) {
        float a = __ldg(&bc2[0]);
        #pragma unroll
        for (int c = 0; c < 8; c++) {
            #pragma unroll
            for (int k = 0; k < 14; k++)
                a += c1[c*38 + tid + k] * __ldg(&Wc2[c*14 + k]);
        }
        float dt = 4.0f / 250.0f;
        out[n*25 + tid] = u[n*25 + 24] + (float)(tid + 1) * dt * a;
    }
}

// ---------------- host ----------------
extern "C" void kernel_launch(void* const* d_in, const int* in_sizes, int n_in,
                              void* d_out, int out_size) {
    const float* u     = (const float*)d_in[0];
    const float* pos   = (const float*)d_in[1];
    const int*   eidx  = (const int*)d_in[2];
    const int*   batch = (const int*)d_in[3];
    const float* We1 = (const float*)d_in[4];
    const float* be1 = (const float*)d_in[5];
    const float* We2 = (const float*)d_in[6];
    const float* be2 = (const float*)d_in[7];
    const float* Wm1 = (const float*)d_in[8];
    const float* bm1 = (const float*)d_in[9];
    const float* Wm2 = (const float*)d_in[10];
    const float* bm2 = (const float*)d_in[11];
    const float* Wu1 = (const float*)d_in[12];
    const float* bu1 = (const float*)d_in[13];
    const float* Wu2 = (const float*)d_in[14];
    const float* bu2 = (const float*)d_in[15];
    const float* Wc1 = (const float*)d_in[16];
    const float* bc1 = (const float*)d_in[17];
    const float* Wc2 = (const float*)d_in[18];
    const float* bc2 = (const float*)d_in[19];
    float* out = (float*)d_out;

    void *a_h = 0, *a_t1 = 0, *a_wm2h = 0, *a_wph = 0, *a_wqh = 0, *a_wu1h = 0, *a_wu2h = 0;
    cudaGetSymbolAddress(&a_h,    g_h);
    cudaGetSymbolAddress(&a_t1,   g_t1);
    cudaGetSymbolAddress(&a_wm2h, g_Wm2h);
    cudaGetSymbolAddress(&a_wph,  g_WPh);
    cudaGetSymbolAddress(&a_wqh,  g_WQh);
    cudaGetSymbolAddress(&a_wu1h, g_Wu1h);
    cudaGetSymbolAddress(&a_wu2h, g_Wu2h);
    float*  h    = (float*)a_h;
    float*  t1   = (float*)a_t1;
    __half* Wm2h = (__half*)a_wm2h;
    __half* WPh  = (__half*)a_wph;
    __half* WQh  = (__half*)a_wqh;
    __half* Wu1h = (__half*)a_wu1h;
    __half* Wu2h = (__half*)a_wu2h;

    int MLP_SMEM_128 = (128*136 + 64*136) * 2;
    cudaFuncSetAttribute(mlp16, cudaFuncAttributeMaxDynamicSharedMemorySize, MLP_SMEM_128);
    cudaFuncSetAttribute(pq_kernel, cudaFuncAttributeMaxDynamicSharedMemorySize, PQ_SMEM);
    cudaFuncSetAttribute(update_kernel, cudaFuncAttributeMaxDynamicSharedMemorySize, UPD_SMEM);
    cudaFuncSetAttribute(edge_kernel, cudaFuncAttributeMaxDynamicSharedMemorySize, EDGE_SMEM);

    convert_wm2<<<(LL*HH*HH/2)/256, 256>>>(Wm2);
    build_pq_w<<<(LL*160*128 + 255)/256, 256>>>(Wm1, bm1);
    build_u_w<<<(LL*256*128 + 255)/256, 256>>>(Wu1, Wu2);
    zero_prep<<<NN/256, 256>>>();
    init_stats<<<(BB*HH + 255)/256, 256>>>();
    prep_node<<<NN/256, 256>>>(pos, batch);
    prep_edge<<<EE/256, 256>>>(eidx);
    fin_cnt<<<NN/256, 256>>>();

    encoder1<<<NN, 128>>>(u, We1, be1);
    mlp16<<<NN/64, 256, MLP_SMEM_128>>>(t1, We2, be2, h);

    for (int l = 0; l < LL; l++) {
        pq_kernel<<<NN/64, 256, PQ_SMEM>>>(WPh + (size_t)l*160*128, WQh + (size_t)l*160*128, u);

        edge_kernel<<<EDGE_GRID, 256, EDGE_SMEM>>>(eidx, Wm2h + (size_t)l*HH*HH, bm2 + l*128);

        update_kernel<<<UPD_GRID, 256, UPD_SMEM>>>(Wu1h + (size_t)l*256*128,
                                                   Wu1 + (size_t)l*257*128 + 256*128,
                                                   bu1 + l*128,
                                                   Wu2h + (size_t)l*128*128,
                                                   bu2 + l*128);
    }

    decoder<<<NN, 64>>>(u, Wc1, bc1, Wc2, bc2, out);
}